// round 13
// baseline (speedup 1.0000x reference)
#include <cuda_runtime.h>
#include <cuda_bf16.h>
#include <math.h>
#include <stdint.h>

#define NB   32768
#define IND  336
#define HD   256
#define NE   16
#define NACT 64

// ---------------- device scratch ----------------
__device__ float g_inp[(size_t)NB * IND];
__device__ float g_cskip[NB];
__device__ float g_cout[NB];
__device__ int   g_count[NE];
__device__ float g_entropy;
__device__ int   g_bucket[NE * NB];             // row | slot<<16
__device__ float g_bw[NE * NB];
__device__ float g_eout[(size_t)NB * 4 * HD];   // per-(row,slot) weighted expert out

// packed weights [e][kstep][t][n]: uint4 = { pair(8ks+t): {hi,lo}, pair(8ks+t+4): {hi,lo} }
__device__ __align__(16) uint4 wq1[NE * 21 * 4 * HD];
__device__ __align__(16) uint4 wq2[NE * 16 * 4 * HD];
__device__ __align__(16) uint4 wq3[NE * 16 * 4 * HD];

__device__ __forceinline__ float mishf(float v) {
    if (v > 20.f) return v;
    float u = __expf(v);
    float w = 1.f + u;
    w = w * w;
    return v * __fdividef(w - 1.f, w + 1.f);
}

// ---------------- packing helpers ----------------
__device__ __forceinline__ uint2 pack2(float a, float b) {
    __nv_bfloat16 ha = __float2bfloat16_rn(a), hb = __float2bfloat16_rn(b);
    __nv_bfloat16 la = __float2bfloat16_rn(a - __bfloat162float(ha));
    __nv_bfloat16 lb = __float2bfloat16_rn(b - __bfloat162float(hb));
    uint2 r;
    r.x = (uint32_t)*(unsigned short*)&ha | ((uint32_t)*(unsigned short*)&hb << 16);
    r.y = (uint32_t)*(unsigned short*)&la | ((uint32_t)*(unsigned short*)&lb << 16);
    return r;
}

// ---------------- mma.sync (baseline PTX) ----------------
__device__ __forceinline__ void mma_bf16(float* c, const uint32_t* a, uint32_t b0, uint32_t b1) {
    asm volatile(
        "mma.sync.aligned.m16n8k16.row.col.f32.bf16.bf16.f32 "
        "{%0,%1,%2,%3}, {%4,%5,%6,%7}, {%8,%9}, {%0,%1,%2,%3};"
        : "+f"(c[0]), "+f"(c[1]), "+f"(c[2]), "+f"(c[3])
        : "r"(a[0]), "r"(a[1]), "r"(a[2]), "r"(a[3]), "r"(b0), "r"(b1));
}

// ---------------- packed fp32x2 FMA machinery (gate kernel) ----------------
#define FMA2(d, a, b) asm("fma.rn.f32x2 %0, %1, %2, %0;" : "+l"(d) : "l"(a), "l"(b))
__device__ __forceinline__ unsigned long long dup2(float v) {
    unsigned long long r;
    asm("mov.b64 %0, {%1, %1};" : "=l"(r) : "r"(__float_as_uint(v)));
    return r;
}
__device__ __forceinline__ float2 unpack2(unsigned long long v) {
    float2 r;
    asm("mov.b64 {%0, %1}, %2;" : "=f"(r.x), "=f"(r.y) : "l"(v));
    return r;
}

template<int LDA>
__device__ __forceinline__ void gemm64x256p(
    const float* __restrict__ A, int K,
    const float* __restrict__ Wg, float* __restrict__ Ws0, float* __restrict__ Ws1,
    unsigned long long (&acc)[8][4], int ty, int tx, int tid)
{
#pragma unroll
    for (int mi = 0; mi < 8; mi++)
#pragma unroll
        for (int ni = 0; ni < 4; ni++) acc[mi][ni] = 0ull;

    const float* Abase = A + ty * 8 * LDA;
    const int ntiles = (K + 31) >> 5;
    const int tx4 = tx << 2;

    float4 pf[8];
    int pr[8], pc[8];
#pragma unroll
    for (int i = 0; i < 8; i++) {
        int f4 = i * 256 + tid;
        pr[i] = f4 >> 6;
        pc[i] = (f4 & 63) << 2;
    }
#pragma unroll
    for (int i = 0; i < 8; i++) {
        int k = pr[i];
        pf[i] = (k < K) ? *(const float4*)&Wg[(size_t)k * 256 + pc[i]]
                        : make_float4(0.f, 0.f, 0.f, 0.f);
    }
    __syncthreads();

    for (int t = 0; t < ntiles; t++) {
        float* Ws = (t & 1) ? Ws1 : Ws0;
#pragma unroll
        for (int i = 0; i < 8; i++)
            *(float4*)&Ws[pr[i] * 256 + pc[i]] = pf[i];
        __syncthreads();
        if (t + 1 < ntiles) {
            int kt = (t + 1) << 5;
#pragma unroll
            for (int i = 0; i < 8; i++) {
                int k = kt + pr[i];
                pf[i] = (k < K) ? *(const float4*)&Wg[(size_t)k * 256 + pc[i]]
                                : make_float4(0.f, 0.f, 0.f, 0.f);
            }
        }
        int kt = t << 5;
        int kc = min(32, K - kt);
        const float* Ap = Abase + kt;
        for (int k = 0; k < kc; k += 2) {
            float2 a01[8];
#pragma unroll
            for (int mi = 0; mi < 8; mi++)
                a01[mi] = *(const float2*)&Ap[mi * LDA + k];
#pragma unroll
            for (int kk = 0; kk < 2; kk++) {
                const float* wrow = &Ws[(k + kk) * 256];
                ulonglong2 bb0 = *(const ulonglong2*)&wrow[tx4];
                ulonglong2 bb1 = *(const ulonglong2*)&wrow[128 + tx4];
#pragma unroll
                for (int mi = 0; mi < 8; mi++) {
                    unsigned long long a2 = dup2(kk ? a01[mi].y : a01[mi].x);
                    FMA2(acc[mi][0], a2, bb0.x);
                    FMA2(acc[mi][1], a2, bb0.y);
                    FMA2(acc[mi][2], a2, bb1.x);
                    FMA2(acc[mi][3], a2, bb1.y);
                }
            }
        }
    }
}

// ---------------- kernel 0: pack expert weights to [e][ks][t][n] uint4 ----------------
__global__ void wconv_kernel(const float* __restrict__ eW1, const float* __restrict__ eW2,
                             const float* __restrict__ eW3)
{
    int i = blockIdx.x * blockDim.x + threadIdx.x;
    if (i < NE * 21 * 4 * HD) {
        int n = i & 255; int r = i >> 8;
        int t = r & 3; int r2 = r >> 2;
        int ks = r2 % 21; int e = r2 / 21;
        int p0 = ks * 8 + t, p1 = p0 + 4;
        size_t k0 = ((size_t)e * IND + 2 * p0) * HD + n;
        size_t k1 = ((size_t)e * IND + 2 * p1) * HD + n;
        uint2 a = pack2(eW1[k0], eW1[k0 + HD]);
        uint2 b = pack2(eW1[k1], eW1[k1 + HD]);
        wq1[i] = make_uint4(a.x, a.y, b.x, b.y);
    }
    if (i < NE * 16 * 4 * HD) {
        int n = i & 255; int r = i >> 8;
        int t = r & 3; int r2 = r >> 2;
        int ks = r2 & 15; int e = r2 >> 4;
        int p0 = ks * 8 + t, p1 = p0 + 4;
        size_t k0 = ((size_t)e * HD + 2 * p0) * HD + n;
        size_t k1 = ((size_t)e * HD + 2 * p1) * HD + n;
        uint2 a2 = pack2(eW2[k0], eW2[k0 + HD]);
        uint2 b2 = pack2(eW2[k1], eW2[k1 + HD]);
        wq2[i] = make_uint4(a2.x, a2.y, b2.x, b2.y);
        uint2 a3 = pack2(eW3[k0], eW3[k0 + HD]);
        uint2 b3 = pack2(eW3[k1], eW3[k1 + HD]);
        wq3[i] = make_uint4(a3.x, a3.y, b3.x, b3.y);
    }
}

// ---------------- kernel 1: per-row prep ----------------
__global__ void prep_kernel(
    const float* __restrict__ x, const float* __restrict__ sigma,
    const float* __restrict__ state,
    const float* __restrict__ tW1, const float* __restrict__ tb1,
    const float* __restrict__ tW2, const float* __restrict__ tb2)
{
    if (blockIdx.x == 0 && threadIdx.x < NE) g_count[threadIdx.x] = 0;
    if (blockIdx.x == 0 && threadIdx.x == NE) g_entropy = 0.f;

    int wid  = (blockIdx.x * blockDim.x + threadIdx.x) >> 5;
    int lane = threadIdx.x & 31;
    if (wid >= NB) return;
    int r = wid;

    float sg  = __ldg(&sigma[r]);
    float sd2 = 0.25f;
    float d   = sg - 0.002f;
    float cskip = sd2 / (d * d + sd2);
    float inv = rsqrtf(sg * sg + sd2);
    float cout = d * 0.5f * inv;
    float cin  = inv;
    float rt   = 250.0f * logf(sg + 1e-44f);

    const float FR[8] = { 1.0f, 0.26826957952797246f, 0.07196856730011519f,
                          0.019306977288832496f, 0.005179474679231212f,
                          0.0013894954943731375f, 0.00037275937203149404f,
                          0.0001f };
    float pe[16];
#pragma unroll
    for (int i = 0; i < 8; i++) {
        float s, c;
        sincosf(rt * FR[i], &s, &c);
        pe[i] = s; pe[i + 8] = c;
    }
    float h1 = __ldg(&tb1[lane]);
#pragma unroll
    for (int i = 0; i < 16; i++) h1 = fmaf(pe[i], __ldg(&tW1[i * 32 + lane]), h1);
    {
        float sp = (h1 > 20.f) ? h1 : log1pf(expf(h1));
        h1 = h1 * tanhf(sp);
    }
    float tacc = (lane < 16) ? __ldg(&tb2[lane]) : 0.f;
#pragma unroll
    for (int j = 0; j < 32; j++) {
        float hj = __shfl_sync(0xffffffffu, h1, j);
        if (lane < 16) tacc = fmaf(hj, __ldg(&tW2[j * 16 + lane]), tacc);
    }
    float* row = g_inp + (size_t)r * IND;
    row[lane]      = cin * __ldg(&x[r * 64 + lane]);
    row[32 + lane] = cin * __ldg(&x[r * 64 + 32 + lane]);
    if (lane < 16) row[64 + lane] = tacc;
#pragma unroll
    for (int i = 0; i < 8; i++)
        row[80 + lane + i * 32] = __ldg(&state[r * 256 + lane + i * 32]);
    if (lane == 0) { g_cskip[r] = cskip; g_cout[r] = cout; }
}

// ---------------- kernel 2: gate + softmax + top4 + routing ----------------
__global__ void __launch_bounds__(256, 1) gate_kernel(
    const float* __restrict__ gW1, const float* __restrict__ gb1,
    const float* __restrict__ gW2, const float* __restrict__ gb2)
{
    extern __shared__ float smem[];
    float* Xs   = smem;                  // 64*340
    float* G1   = Xs + 64 * 340;         // 64*260
    float* Ws0  = G1 + 64 * 260;         // 32*256
    float* Ws1  = Ws0 + 32 * 256;        // 32*256
    float* entA = Ws1 + 32 * 256;        // 1

    int tid = threadIdx.x, ty = tid >> 5, tx = tid & 31;
    int base = blockIdx.x * 64;
    if (tid == 0) *entA = 0.f;
#pragma unroll
    for (int rr = 0; rr < 8; rr++) {
        int m = ty * 8 + rr;
        const float* src = g_inp + (size_t)(base + m) * IND;
        for (int k = tx; k < IND; k += 32) Xs[m * 340 + k] = src[k];
    }
    unsigned long long acc[8][4];
    gemm64x256p<340>(Xs, IND, gW1, Ws0, Ws1, acc, ty, tx, tid);
    {
        const int tx4 = tx << 2;
        float bs[8];
#pragma unroll
        for (int i = 0; i < 4; i++) { bs[i] = __ldg(&gb1[tx4 + i]); bs[4 + i] = __ldg(&gb1[128 + tx4 + i]); }
#pragma unroll
        for (int mi = 0; mi < 8; mi++) {
            float* o = G1 + (ty * 8 + mi) * 260;
            float2 p0 = unpack2(acc[mi][0]);
            float2 p1 = unpack2(acc[mi][1]);
            float2 p2 = unpack2(acc[mi][2]);
            float2 p3 = unpack2(acc[mi][3]);
            float4 v0, v1;
            v0.x = fmaxf(p0.x + bs[0], 0.f); v0.y = fmaxf(p0.y + bs[1], 0.f);
            v0.z = fmaxf(p1.x + bs[2], 0.f); v0.w = fmaxf(p1.y + bs[3], 0.f);
            v1.x = fmaxf(p2.x + bs[4], 0.f); v1.y = fmaxf(p2.y + bs[5], 0.f);
            v1.z = fmaxf(p3.x + bs[6], 0.f); v1.w = fmaxf(p3.y + bs[7], 0.f);
            *(float4*)&o[tx4]       = v0;
            *(float4*)&o[128 + tx4] = v1;
        }
    }
    __syncthreads();

    float* W2s = Ws0;
    for (int i = tid; i < 4096; i += 256) W2s[i] = gW2[i];
    __syncthreads();

    int j = tx & 15, kh = tx >> 4;
    for (int rr = 0; rr < 8; rr++) {
        int m = ty * 8 + rr;
        int row = base + m;
        const float* g1 = &G1[m * 260];
        float s = 0.f;
        int k0 = kh * 128;
#pragma unroll 4
        for (int k = 0; k < 128; k++) s = fmaf(g1[k0 + k], W2s[(k0 + k) * 16 + j], s);
        s += __shfl_down_sync(0xffffffffu, s, 16);
        float gv = s + __ldg(&gb2[j]);
        float p[16];
#pragma unroll
        for (int q = 0; q < 16; q++) p[q] = __shfl_sync(0xffffffffu, gv, q);
        float mx = p[0];
#pragma unroll
        for (int q = 1; q < 16; q++) mx = fmaxf(mx, p[q]);
        float Z = 0.f;
#pragma unroll
        for (int q = 0; q < 16; q++) { p[q] = expf(p[q] - mx); Z += p[q]; }
        float invZ = 1.f / Z;
        float ent = 0.f;
#pragma unroll
        for (int q = 0; q < 16; q++) { p[q] *= invZ; ent -= p[q] * logf(p[q] + 1e-9f); }
        unsigned usedm = 0;
        int   idx[4]; float val[4]; float wsum = 0.f;
#pragma unroll
        for (int s4 = 0; s4 < 4; s4++) {
            int best = 0; float bv = -1.f;
#pragma unroll
            for (int q = 0; q < 16; q++) {
                bool free = !((usedm >> q) & 1u);
                if (free && p[q] > bv) { bv = p[q]; best = q; }
            }
            usedm |= (1u << best);
            idx[s4] = best; val[s4] = bv; wsum += bv;
        }
        float invw = 1.f / (wsum + 1e-9f);
        if (tx < 4) {
            int ee = idx[tx];
            int pos = atomicAdd(&g_count[ee], 1);
            g_bucket[ee * NB + pos] = row | (tx << 16);
            g_bw[ee * NB + pos] = val[tx] * invw;
        }
        if (tx == 0) atomicAdd(entA, ent);
    }
    __syncthreads();
    if (tid == 0) atomicAdd(&g_entropy, *entA);
}

// ---------------- kernel 3: bf16-split HMMA expert MLP, M=32, 3 blocks/SM ----------------
// 8 warps, M=32, warp tile 32x32 (wn=wid, all warps share rows 0..31).
// A smem: uint4 per (slot = ks*4+t, row), row-stride 34 (word-stride 136 = 8 mod 32
// -> conflict-free LDS.128). W fragments via one LDG.128 per nt per k-step.
// Barrier-free K-loop; ~80 regs/thread -> 3 blocks/SM (24 warps/SM).
#define LDA4 34
#define XSM_META (84 * LDA4 * 16)         // 45696
#define XSM_TOTAL (XSM_META + 3584)       // 49280

__global__ void __launch_bounds__(256, 3) expert_kernel(
    const float* __restrict__ eb1, const float* __restrict__ eb2,
    const float* __restrict__ eb3)
{
    extern __shared__ char sm[];
    int e = blockIdx.y;
    int cnt = g_count[e];
    int base = blockIdx.x * 32;
    if (base >= cnt) return;

    int tid = threadIdx.x;
    int lane = tid & 31, wn = tid >> 5;    // warp tile: rows [0,32), cols [wn*32,+32)
    int g = lane >> 2, t = lane & 3;

    int*   srow = (int*)(sm + XSM_META);          // 32 ints
    float* swt  = (float*)(sm + XSM_META + 128);  // 32 floats
    float* sb1  = (float*)(sm + XSM_META + 256);
    float* sb2  = (float*)(sm + XSM_META + 1280);
    float* sb3  = (float*)(sm + XSM_META + 2304);

    if (tid < 32) {
        int gi = base + tid;
        int gj = (gi < cnt) ? gi : (cnt - 1);
        srow[tid] = g_bucket[e * NB + gj];
        swt[tid]  = (gi < cnt) ? g_bw[e * NB + gj] : 0.f;
    }
    sb1[tid] = eb1[e * HD + tid];
    sb2[tid] = eb2[e * HD + tid];
    sb3[tid] = eb3[e * HD + tid];
    __syncthreads();

    // stage layer-1 activations into interleaved uint4 layout (32 rows)
    {
        int r = tid & 31, q = tid >> 5;           // q in [0,8), 21 pairs each
        int rid = srow[r] & 0xFFFF;
        const float2* src = (const float2*)(g_inp + (size_t)rid * IND);
        uint2* A2 = (uint2*)sm;
        for (int p = q * 21; p < q * 21 + 21; p++) {
            float2 v = src[p];
            int s = ((p >> 3) << 2) | (p & 3);
            int half = (p >> 2) & 1;
            A2[(s * LDA4 + r) * 2 + half] = pack2(v.x, v.y);
        }
    }
    __syncthreads();

    float c[2][4][4];
    const int nbase = wn * 32 + g;

    auto run_layer = [&](const uint4* __restrict__ wq, int ksteps) {
#pragma unroll
        for (int a = 0; a < 2; a++)
#pragma unroll
            for (int b = 0; b < 4; b++)
#pragma unroll
                for (int d = 0; d < 4; d++) c[a][b][d] = 0.f;
        const uint4* A4   = (const uint4*)sm + t * LDA4;      // +4*LDA4 per ks
        const uint4* wptr = wq + (size_t)t * HD + nbase;      // +4*HD per ks
        for (int ks = 0; ks < ksteps; ks++) {
            // W fragments: one LDG.128 per nt (issue first, consume after A loads)
            uint4 b[4];
#pragma unroll
            for (int nt = 0; nt < 4; nt++) b[nt] = __ldg(wptr + nt * 8);
            // A fragments: 2 LDS.128 (both k-halves at once)
            uint32_t ah[2][4], al[2][4];
#pragma unroll
            for (int mt = 0; mt < 2; mt++) {
                int row = mt * 16 + g;
                uint4 v0 = A4[row];
                uint4 v1 = A4[row + 8];
                ah[mt][0] = v0.x; al[mt][0] = v0.y;
                ah[mt][1] = v1.x; al[mt][1] = v1.y;
                ah[mt][2] = v0.z; al[mt][2] = v0.w;
                ah[mt][3] = v1.z; al[mt][3] = v1.w;
            }
            // term-outer: 8 independent accumulators between dependent reuses
#pragma unroll
            for (int nt = 0; nt < 4; nt++)
#pragma unroll
                for (int mt = 0; mt < 2; mt++)
                    mma_bf16(c[mt][nt], ah[mt], b[nt].x, b[nt].z);   // hi*hi
#pragma unroll
            for (int nt = 0; nt < 4; nt++)
#pragma unroll
                for (int mt = 0; mt < 2; mt++)
                    mma_bf16(c[mt][nt], ah[mt], b[nt].y, b[nt].w);   // hi*lo
#pragma unroll
            for (int nt = 0; nt < 4; nt++)
#pragma unroll
                for (int mt = 0; mt < 2; mt++)
                    mma_bf16(c[mt][nt], al[mt], b[nt].x, b[nt].z);   // lo*hi
            A4   += 4 * LDA4;
            wptr += 4 * HD;
        }
        __syncthreads();   // all warps done reading A before it is overwritten
    };

    auto write_act = [&](const float* sb) {
        uint2* An = (uint2*)sm;
#pragma unroll
        for (int mt = 0; mt < 2; mt++) {
            int row0 = mt * 16 + g;
#pragma unroll
            for (int nt = 0; nt < 4; nt++) {
                int col = wn * 32 + nt * 8 + 2 * t;
                int p = wn * 16 + nt * 4 + t;
                int s = ((p >> 3) << 2) | (p & 3);
                int half = (p >> 2) & 1;
                float b0 = sb[col], b1 = sb[col + 1];
                An[(s * LDA4 + row0) * 2 + half]     = pack2(mishf(c[mt][nt][0] + b0), mishf(c[mt][nt][1] + b1));
                An[(s * LDA4 + row0 + 8) * 2 + half] = pack2(mishf(c[mt][nt][2] + b0), mishf(c[mt][nt][3] + b1));
            }
        }
        __syncthreads();   // new A visible to all warps
    };

    run_layer(wq1 + (size_t)e * 21 * 4 * HD, 21);
    write_act(sb1);
    run_layer(wq2 + (size_t)e * 16 * 4 * HD, 16);
    write_act(sb2);
    run_layer(wq3 + (size_t)e * 16 * 4 * HD, 16);

    // epilogue: g_eout[row*4+slot][col] = w * mish(C + b3)
#pragma unroll
    for (int mt = 0; mt < 2; mt++) {
#pragma unroll
        for (int half = 0; half < 2; half++) {
            int m = mt * 16 + half * 8 + g;
            int gi = base + m;
            if (gi < cnt) {
                int packed = srow[m];
                int row = packed & 0xFFFF, slot = packed >> 16;
                float w = swt[m];
                float* dst = g_eout + ((size_t)(row * 4 + slot)) * HD;
#pragma unroll
                for (int nt = 0; nt < 4; nt++) {
                    int col = wn * 32 + nt * 8 + 2 * t;
                    float2 o;
                    o.x = w * mishf(c[mt][nt][half * 2 + 0] + sb3[col]);
                    o.y = w * mishf(c[mt][nt][half * 2 + 1] + sb3[col + 1]);
                    *(float2*)&dst[col] = o;
                }
            }
        }
    }
}

// ---------------- kernel 4: combine slots + final linear + epilogue ----------------
__global__ void __launch_bounds__(256, 1) final_kernel(
    const float* __restrict__ x, const float* __restrict__ fW,
    const float* __restrict__ fb, float* __restrict__ out)
{
    extern __shared__ float smem[];
    float* cs  = smem;             // 32*260
    float* fWs = cs + 32 * 260;    // 256*64
    int tid = threadIdx.x;
    int base = blockIdx.x * 32;

    for (int i = tid; i < 4096; i += 256)
        ((float4*)fWs)[i] = ((const float4*)fW)[i];
    for (int idx = tid; idx < 32 * 64; idx += 256) {
        int m = idx >> 6, n4 = (idx & 63) << 2;
        size_t rb = ((size_t)(base + m)) * 4 * HD + n4;
        float4 a = *(const float4*)&g_eout[rb];
        float4 b = *(const float4*)&g_eout[rb + 256];
        float4 c = *(const float4*)&g_eout[rb + 512];
        float4 d = *(const float4*)&g_eout[rb + 768];
        float4 v;
        v.x = a.x + b.x + c.x + d.x;
        v.y = a.y + b.y + c.y + d.y;
        v.z = a.z + b.z + c.z + d.z;
        v.w = a.w + b.w + c.w + d.w;
        *(float4*)&cs[m * 260 + n4] = v;
    }
    __syncthreads();

    int ty = tid >> 4, tx = tid & 15;
    float acc[2][4];
#pragma unroll
    for (int mi = 0; mi < 2; mi++)
#pragma unroll
        for (int ci = 0; ci < 4; ci++) acc[mi][ci] = 0.f;
#pragma unroll 4
    for (int k = 0; k < 256; k++) {
        float4 b = *(const float4*)&fWs[k * 64 + (tx << 2)];
#pragma unroll
        for (int mi = 0; mi < 2; mi++) {
            float a = cs[(ty * 2 + mi) * 260 + k];
            acc[mi][0] = fmaf(a, b.x, acc[mi][0]);
            acc[mi][1] = fmaf(a, b.y, acc[mi][1]);
            acc[mi][2] = fmaf(a, b.z, acc[mi][2]);
            acc[mi][3] = fmaf(a, b.w, acc[mi][3]);
        }
    }
#pragma unroll
    for (int mi = 0; mi < 2; mi++) {
        int row = base + ty * 2 + mi;
        float co = g_cout[row], ck = g_cskip[row];
        float4 xr = *(const float4*)&x[row * 64 + (tx << 2)];
        float4 o;
        o.x = fminf(fmaxf(co * (acc[mi][0] + __ldg(&fb[(tx << 2) + 0])) + ck * xr.x, -1.f), 1.f);
        o.y = fminf(fmaxf(co * (acc[mi][1] + __ldg(&fb[(tx << 2) + 1])) + ck * xr.y, -1.f), 1.f);
        o.z = fminf(fmaxf(co * (acc[mi][2] + __ldg(&fb[(tx << 2) + 2])) + ck * xr.z, -1.f), 1.f);
        o.w = fminf(fmaxf(co * (acc[mi][3] + __ldg(&fb[(tx << 2) + 3])) + ck * xr.w, -1.f), 1.f);
        *(float4*)&out[row * 64 + (tx << 2)] = o;
    }
}

// ---------------- kernel 5: aux loss ----------------
__global__ void aux_kernel(float* __restrict__ out, int out_size)
{
    if (threadIdx.x == 0 && out_size > NB * NACT) {
        float load[NE], mean = 0.f;
#pragma unroll
        for (int e = 0; e < NE; e++) { load[e] = (float)g_count[e] / (32768.0f + 1e-9f); mean += load[e]; }
        mean *= (1.0f / NE);
        float var = 0.f;
#pragma unroll
        for (int e = 0; e < NE; e++) { float d = load[e] - mean; var += d * d; }
        var *= (1.0f / (NE - 1));
        out[NB * NACT] = var + g_entropy / 32768.0f;
    }
}

extern "C" void kernel_launch(void* const* d_in, const int* in_sizes, int n_in,
                              void* d_out, int out_size)
{
    const float* x     = (const float*)d_in[0];
    const float* sigma = (const float*)d_in[1];
    const float* state = (const float*)d_in[2];
    const float* tW1 = (const float*)d_in[3];
    const float* tb1 = (const float*)d_in[4];
    const float* tW2 = (const float*)d_in[5];
    const float* tb2 = (const float*)d_in[6];
    const float* gW1 = (const float*)d_in[7];
    const float* gb1 = (const float*)d_in[8];
    const float* gW2 = (const float*)d_in[9];
    const float* gb2 = (const float*)d_in[10];
    const float* eW1 = (const float*)d_in[11];
    const float* eb1 = (const float*)d_in[12];
    const float* eW2 = (const float*)d_in[13];
    const float* eb2 = (const float*)d_in[14];
    const float* eW3 = (const float*)d_in[15];
    const float* eb3 = (const float*)d_in[16];
    const float* fW  = (const float*)d_in[17];
    const float* fb  = (const float*)d_in[18];
    float* out = (float*)d_out;

    const int gateSmem = (64 * 340 + 64 * 260 + 2 * 32 * 256 + 16) * 4;
    const int finSmem  = (32 * 260 + 256 * 64 + 16) * 4;
    cudaFuncSetAttribute(gate_kernel,   cudaFuncAttributeMaxDynamicSharedMemorySize, gateSmem);
    cudaFuncSetAttribute(expert_kernel, cudaFuncAttributeMaxDynamicSharedMemorySize, XSM_TOTAL);
    cudaFuncSetAttribute(final_kernel,  cudaFuncAttributeMaxDynamicSharedMemorySize, finSmem);

    prep_kernel<<<NB / 8, 256>>>(x, sigma, state, tW1, tb1, tW2, tb2);
    wconv_kernel<<<(NE * 21 * 4 * HD + 255) / 256, 256>>>(eW1, eW2, eW3);
    gate_kernel<<<NB / 64, 256, gateSmem>>>(gW1, gb1, gW2, gb2);
    expert_kernel<<<dim3(NB / 32, NE), 256, XSM_TOTAL>>>(eb1, eb2, eb3);
    final_kernel<<<NB / 32, 256, finSmem>>>(x, fW, fb, out);
    aux_kernel<<<1, 32>>>(out, out_size);
}

// round 14
// speedup vs baseline: 1.0843x; 1.0843x over previous
#include <cuda_runtime.h>
#include <cuda_bf16.h>
#include <math.h>
#include <stdint.h>

#define NB   32768
#define IND  336
#define HD   256
#define NE   16
#define NACT 64

// ---------------- device scratch ----------------
__device__ float g_inp[(size_t)NB * IND];
__device__ float g_g1[(size_t)NB * HD];         // gate layer-1 relu output
__device__ float g_cskip[NB];
__device__ float g_cout[NB];
__device__ int   g_count[NE];
__device__ float g_entropy;
__device__ int   g_bucket[NE * NB];             // row | slot<<16
__device__ float g_bw[NE * NB];
__device__ float g_eout[(size_t)NB * 4 * HD];   // per-(row,slot) weighted expert out

// packed weights [e][kstep][t][n]: uint4 = { pair(8ks+t): {hi,lo}, pair(8ks+t+4): {hi,lo} }
__device__ __align__(16) uint4 wq1[NE * 21 * 4 * HD];
__device__ __align__(16) uint4 wq2[NE * 16 * 4 * HD];
__device__ __align__(16) uint4 wq3[NE * 16 * 4 * HD];

__device__ __forceinline__ float mishf(float v) {
    if (v > 20.f) return v;
    float u = __expf(v);
    float w = 1.f + u;
    w = w * w;
    return v * __fdividef(w - 1.f, w + 1.f);
}

// ---------------- packing helpers ----------------
__device__ __forceinline__ uint2 pack2(float a, float b) {
    __nv_bfloat16 ha = __float2bfloat16_rn(a), hb = __float2bfloat16_rn(b);
    __nv_bfloat16 la = __float2bfloat16_rn(a - __bfloat162float(ha));
    __nv_bfloat16 lb = __float2bfloat16_rn(b - __bfloat162float(hb));
    uint2 r;
    r.x = (uint32_t)*(unsigned short*)&ha | ((uint32_t)*(unsigned short*)&hb << 16);
    r.y = (uint32_t)*(unsigned short*)&la | ((uint32_t)*(unsigned short*)&lb << 16);
    return r;
}

// ---------------- mma.sync (baseline PTX) ----------------
__device__ __forceinline__ void mma_bf16(float* c, const uint32_t* a, uint32_t b0, uint32_t b1) {
    asm volatile(
        "mma.sync.aligned.m16n8k16.row.col.f32.bf16.bf16.f32 "
        "{%0,%1,%2,%3}, {%4,%5,%6,%7}, {%8,%9}, {%0,%1,%2,%3};"
        : "+f"(c[0]), "+f"(c[1]), "+f"(c[2]), "+f"(c[3])
        : "r"(a[0]), "r"(a[1]), "r"(a[2]), "r"(a[3]), "r"(b0), "r"(b1));
}

// ---------------- packed fp32x2 FMA machinery (gate) ----------------
#define FMA2(d, a, b) asm("fma.rn.f32x2 %0, %1, %2, %0;" : "+l"(d) : "l"(a), "l"(b))
__device__ __forceinline__ unsigned long long dup2(float v) {
    unsigned long long r;
    asm("mov.b64 %0, {%1, %1};" : "=l"(r) : "r"(__float_as_uint(v)));
    return r;
}
__device__ __forceinline__ float2 unpack2(unsigned long long v) {
    float2 r;
    asm("mov.b64 {%0, %1}, %2;" : "=f"(r.x), "=f"(r.y) : "l"(v));
    return r;
}

// 32-row x 256-col FFMA2 GEMM; warp ty owns rows ty*4..+3; lane tx owns cols
// tx*4..+3 and 128+tx*4..+3. W tile double-buffered, one barrier per tile.
template<int LDA>
__device__ __forceinline__ void gemm32x256p(
    const float* __restrict__ A, int K,
    const float* __restrict__ Wg, float* __restrict__ Ws0, float* __restrict__ Ws1,
    unsigned long long (&acc)[4][4], int ty, int tx, int tid)
{
#pragma unroll
    for (int mi = 0; mi < 4; mi++)
#pragma unroll
        for (int ni = 0; ni < 4; ni++) acc[mi][ni] = 0ull;

    const float* Abase = A + ty * 4 * LDA;
    const int ntiles = (K + 31) >> 5;
    const int tx4 = tx << 2;

    float4 pf[8];
    int pr[8], pc[8];
#pragma unroll
    for (int i = 0; i < 8; i++) {
        int f4 = i * 256 + tid;
        pr[i] = f4 >> 6;
        pc[i] = (f4 & 63) << 2;
    }
#pragma unroll
    for (int i = 0; i < 8; i++) {
        int k = pr[i];
        pf[i] = (k < K) ? *(const float4*)&Wg[(size_t)k * 256 + pc[i]]
                        : make_float4(0.f, 0.f, 0.f, 0.f);
    }
    __syncthreads();

    for (int t = 0; t < ntiles; t++) {
        float* Ws = (t & 1) ? Ws1 : Ws0;
#pragma unroll
        for (int i = 0; i < 8; i++)
            *(float4*)&Ws[pr[i] * 256 + pc[i]] = pf[i];
        __syncthreads();
        if (t + 1 < ntiles) {
            int kt = (t + 1) << 5;
#pragma unroll
            for (int i = 0; i < 8; i++) {
                int k = kt + pr[i];
                pf[i] = (k < K) ? *(const float4*)&Wg[(size_t)k * 256 + pc[i]]
                                : make_float4(0.f, 0.f, 0.f, 0.f);
            }
        }
        int kt = t << 5;
        int kc = min(32, K - kt);
        const float* Ap = Abase + kt;
        for (int k = 0; k < kc; k += 2) {
            float2 a01[4];
#pragma unroll
            for (int mi = 0; mi < 4; mi++)
                a01[mi] = *(const float2*)&Ap[mi * LDA + k];
#pragma unroll
            for (int kk = 0; kk < 2; kk++) {
                const float* wrow = &Ws[(k + kk) * 256];
                ulonglong2 bb0 = *(const ulonglong2*)&wrow[tx4];
                ulonglong2 bb1 = *(const ulonglong2*)&wrow[128 + tx4];
#pragma unroll
                for (int mi = 0; mi < 4; mi++) {
                    unsigned long long a2 = dup2(kk ? a01[mi].y : a01[mi].x);
                    FMA2(acc[mi][0], a2, bb0.x);
                    FMA2(acc[mi][1], a2, bb0.y);
                    FMA2(acc[mi][2], a2, bb1.x);
                    FMA2(acc[mi][3], a2, bb1.y);
                }
            }
        }
    }
}

// ---------------- kernel 0: pack expert weights to [e][ks][t][n] uint4 ----------------
__global__ void wconv_kernel(const float* __restrict__ eW1, const float* __restrict__ eW2,
                             const float* __restrict__ eW3)
{
    int i = blockIdx.x * blockDim.x + threadIdx.x;
    if (i < NE * 21 * 4 * HD) {
        int n = i & 255; int r = i >> 8;
        int t = r & 3; int r2 = r >> 2;
        int ks = r2 % 21; int e = r2 / 21;
        int p0 = ks * 8 + t, p1 = p0 + 4;
        size_t k0 = ((size_t)e * IND + 2 * p0) * HD + n;
        size_t k1 = ((size_t)e * IND + 2 * p1) * HD + n;
        uint2 a = pack2(eW1[k0], eW1[k0 + HD]);
        uint2 b = pack2(eW1[k1], eW1[k1 + HD]);
        wq1[i] = make_uint4(a.x, a.y, b.x, b.y);
    }
    if (i < NE * 16 * 4 * HD) {
        int n = i & 255; int r = i >> 8;
        int t = r & 3; int r2 = r >> 2;
        int ks = r2 & 15; int e = r2 >> 4;
        int p0 = ks * 8 + t, p1 = p0 + 4;
        size_t k0 = ((size_t)e * HD + 2 * p0) * HD + n;
        size_t k1 = ((size_t)e * HD + 2 * p1) * HD + n;
        uint2 a2 = pack2(eW2[k0], eW2[k0 + HD]);
        uint2 b2 = pack2(eW2[k1], eW2[k1 + HD]);
        wq2[i] = make_uint4(a2.x, a2.y, b2.x, b2.y);
        uint2 a3 = pack2(eW3[k0], eW3[k0 + HD]);
        uint2 b3 = pack2(eW3[k1], eW3[k1 + HD]);
        wq3[i] = make_uint4(a3.x, a3.y, b3.x, b3.y);
    }
}

// ---------------- kernel 1: per-row prep ----------------
__global__ void prep_kernel(
    const float* __restrict__ x, const float* __restrict__ sigma,
    const float* __restrict__ state,
    const float* __restrict__ tW1, const float* __restrict__ tb1,
    const float* __restrict__ tW2, const float* __restrict__ tb2)
{
    if (blockIdx.x == 0 && threadIdx.x < NE) g_count[threadIdx.x] = 0;
    if (blockIdx.x == 0 && threadIdx.x == NE) g_entropy = 0.f;

    int wid  = (blockIdx.x * blockDim.x + threadIdx.x) >> 5;
    int lane = threadIdx.x & 31;
    if (wid >= NB) return;
    int r = wid;

    float sg  = __ldg(&sigma[r]);
    float sd2 = 0.25f;
    float d   = sg - 0.002f;
    float cskip = sd2 / (d * d + sd2);
    float inv = rsqrtf(sg * sg + sd2);
    float cout = d * 0.5f * inv;
    float cin  = inv;
    float rt   = 250.0f * logf(sg + 1e-44f);

    const float FR[8] = { 1.0f, 0.26826957952797246f, 0.07196856730011519f,
                          0.019306977288832496f, 0.005179474679231212f,
                          0.0013894954943731375f, 0.00037275937203149404f,
                          0.0001f };
    float pe[16];
#pragma unroll
    for (int i = 0; i < 8; i++) {
        float s, c;
        sincosf(rt * FR[i], &s, &c);
        pe[i] = s; pe[i + 8] = c;
    }
    float h1 = __ldg(&tb1[lane]);
#pragma unroll
    for (int i = 0; i < 16; i++) h1 = fmaf(pe[i], __ldg(&tW1[i * 32 + lane]), h1);
    {
        float sp = (h1 > 20.f) ? h1 : log1pf(expf(h1));
        h1 = h1 * tanhf(sp);
    }
    float tacc = (lane < 16) ? __ldg(&tb2[lane]) : 0.f;
#pragma unroll
    for (int j = 0; j < 32; j++) {
        float hj = __shfl_sync(0xffffffffu, h1, j);
        if (lane < 16) tacc = fmaf(hj, __ldg(&tW2[j * 16 + lane]), tacc);
    }
    float* row = g_inp + (size_t)r * IND;
    row[lane]      = cin * __ldg(&x[r * 64 + lane]);
    row[32 + lane] = cin * __ldg(&x[r * 64 + 32 + lane]);
    if (lane < 16) row[64 + lane] = tacc;
#pragma unroll
    for (int i = 0; i < 8; i++)
        row[80 + lane + i * 32] = __ldg(&state[r * 256 + lane + i * 32]);
    if (lane == 0) { g_cskip[r] = cskip; g_cout[r] = cout; }
}

// ---------------- kernel 2a: gate layer-1 GEMM (32 rows/block, 2 blocks/SM) ----------------
__global__ void __launch_bounds__(256, 2) gate1_kernel(
    const float* __restrict__ gW1, const float* __restrict__ gb1)
{
    extern __shared__ float smem[];
    float* Xs  = smem;              // 32*340
    float* Ws0 = Xs + 32 * 340;     // 32*256
    float* Ws1 = Ws0 + 32 * 256;    // 32*256

    int tid = threadIdx.x, ty = tid >> 5, tx = tid & 31;
    int base = blockIdx.x * 32;
    {
        int r = tid & 31, q = tid >> 5;   // 8 threads per row, 42 floats each
        const float* src = g_inp + (size_t)(base + r) * IND;
        for (int k = q * 42; k < q * 42 + 42; k++) Xs[r * 340 + k] = src[k];
    }
    unsigned long long acc[4][4];
    gemm32x256p<340>(Xs, IND, gW1, Ws0, Ws1, acc, ty, tx, tid);

    const int tx4 = tx << 2;
    float bs[8];
#pragma unroll
    for (int i = 0; i < 4; i++) { bs[i] = __ldg(&gb1[tx4 + i]); bs[4 + i] = __ldg(&gb1[128 + tx4 + i]); }
#pragma unroll
    for (int mi = 0; mi < 4; mi++) {
        float* o = g_g1 + (size_t)(base + ty * 4 + mi) * HD;
        float2 p0 = unpack2(acc[mi][0]);
        float2 p1 = unpack2(acc[mi][1]);
        float2 p2 = unpack2(acc[mi][2]);
        float2 p3 = unpack2(acc[mi][3]);
        float4 v0, v1;
        v0.x = fmaxf(p0.x + bs[0], 0.f); v0.y = fmaxf(p0.y + bs[1], 0.f);
        v0.z = fmaxf(p1.x + bs[2], 0.f); v0.w = fmaxf(p1.y + bs[3], 0.f);
        v1.x = fmaxf(p2.x + bs[4], 0.f); v1.y = fmaxf(p2.y + bs[5], 0.f);
        v1.z = fmaxf(p3.x + bs[6], 0.f); v1.w = fmaxf(p3.y + bs[7], 0.f);
        *(float4*)&o[tx4]       = v0;
        *(float4*)&o[128 + tx4] = v1;
    }
}

// ---------------- kernel 2b: gate layer-2 + softmax + top4 + routing ----------------
__global__ void __launch_bounds__(256, 2) gate2_kernel(
    const float* __restrict__ gW2, const float* __restrict__ gb2)
{
    extern __shared__ float smem[];
    float* G1s  = smem;             // 64*256
    float* W2s  = G1s + 64 * 256;   // 256*16
    float* entA = W2s + 4096;       // 1

    int tid = threadIdx.x, ty = tid >> 5, tx = tid & 31;
    int base = blockIdx.x * 64;
    if (tid == 0) *entA = 0.f;
    for (int i = tid; i < 4096; i += 256) {
        ((float4*)G1s)[i] = *(const float4*)&g_g1[(size_t)base * HD + i * 4];
        W2s[i] = gW2[i];
    }
    __syncthreads();

    int j = tx & 15, kh = tx >> 4;
    for (int rr = 0; rr < 8; rr++) {
        int m = ty * 8 + rr;
        int row = base + m;
        const float* g1 = &G1s[m * 256];
        float s = 0.f;
        int k0 = kh * 128;
#pragma unroll 4
        for (int k = 0; k < 128; k++) s = fmaf(g1[k0 + k], W2s[(k0 + k) * 16 + j], s);
        s += __shfl_down_sync(0xffffffffu, s, 16);
        float gv = s + __ldg(&gb2[j]);
        float p[16];
#pragma unroll
        for (int q = 0; q < 16; q++) p[q] = __shfl_sync(0xffffffffu, gv, q);
        float mx = p[0];
#pragma unroll
        for (int q = 1; q < 16; q++) mx = fmaxf(mx, p[q]);
        float Z = 0.f;
#pragma unroll
        for (int q = 0; q < 16; q++) { p[q] = expf(p[q] - mx); Z += p[q]; }
        float invZ = 1.f / Z;
        float ent = 0.f;
#pragma unroll
        for (int q = 0; q < 16; q++) { p[q] *= invZ; ent -= p[q] * logf(p[q] + 1e-9f); }
        unsigned usedm = 0;
        int   idx[4]; float val[4]; float wsum = 0.f;
#pragma unroll
        for (int s4 = 0; s4 < 4; s4++) {
            int best = 0; float bv = -1.f;
#pragma unroll
            for (int q = 0; q < 16; q++) {
                bool free = !((usedm >> q) & 1u);
                if (free && p[q] > bv) { bv = p[q]; best = q; }
            }
            usedm |= (1u << best);
            idx[s4] = best; val[s4] = bv; wsum += bv;
        }
        float invw = 1.f / (wsum + 1e-9f);
        if (tx < 4) {
            int ee = idx[tx];
            int pos = atomicAdd(&g_count[ee], 1);
            g_bucket[ee * NB + pos] = row | (tx << 16);
            g_bw[ee * NB + pos] = val[tx] * invw;
        }
        if (tx == 0) atomicAdd(entA, ent);
    }
    __syncthreads();
    if (tid == 0) atomicAdd(&g_entropy, *entA);
}

// ---------------- kernel 3: bf16-split HMMA expert MLP (R10 config) ----------------
// 8 warps, M=64, warp tile 32x64. A in smem [pair][row] stride 68 u64
// (conflict-free). W via one LDG.128 per nt per k-step; barrier-free K-loop;
// single A buffer (95KB smem -> 2 blocks/SM).
#define LDA_U 68
#define XSM_META (168 * LDA_U * 8)        // 91392
#define XSM_TOTAL (XSM_META + 3584)

__global__ void __launch_bounds__(256, 2) expert_kernel(
    const float* __restrict__ eb1, const float* __restrict__ eb2,
    const float* __restrict__ eb3)
{
    extern __shared__ char sm[];
    int e = blockIdx.y;
    int cnt = g_count[e];
    int base = blockIdx.x * 64;
    if (base >= cnt) return;

    int tid = threadIdx.x;
    int lane = tid & 31, wid = tid >> 5;
    int wm = wid >> 2, wn = wid & 3;       // warp tile: rows [wm*32,+32), cols [wn*64,+64)
    int g = lane >> 2, t = lane & 3;

    int*   srow = (int*)(sm + XSM_META);
    float* swt  = (float*)(sm + XSM_META + 256);
    float* sb1  = (float*)(sm + XSM_META + 512);
    float* sb2  = (float*)(sm + XSM_META + 1536);
    float* sb3  = (float*)(sm + XSM_META + 2560);

    if (tid < 64) {
        int gi = base + tid;
        int gj = (gi < cnt) ? gi : (cnt - 1);
        srow[tid] = g_bucket[e * NB + gj];
        swt[tid]  = (gi < cnt) ? g_bw[e * NB + gj] : 0.f;
    }
    sb1[tid] = eb1[e * HD + tid];
    sb2[tid] = eb2[e * HD + tid];
    sb3[tid] = eb3[e * HD + tid];
    __syncthreads();

    // stage layer-1 activations: A[pair][row]
    {
        int r = tid & 63, q = tid >> 6;           // q in [0,4), 42 pairs each
        int rid = srow[r] & 0xFFFF;
        const float2* src = (const float2*)(g_inp + (size_t)rid * IND);
        uint2* A0 = (uint2*)sm;
        for (int p = q * 42; p < q * 42 + 42; p++) {
            float2 v = src[p];
            A0[p * LDA_U + r] = pack2(v.x, v.y);
        }
    }
    __syncthreads();

    float c[2][8][4];
    const int nbase = wn * 64 + g;
    const int rowA  = wm * 32 + g;

    auto run_layer = [&](const uint4* __restrict__ wq, int ksteps) {
#pragma unroll
        for (int a = 0; a < 2; a++)
#pragma unroll
            for (int b = 0; b < 8; b++)
#pragma unroll
                for (int d = 0; d < 4; d++) c[a][b][d] = 0.f;
        const uint2* aptr = (const uint2*)sm + t * LDA_U;     // advances 8*LDA_U per ks
        const uint4* wptr = wq + (size_t)t * HD + nbase;      // advances 4*HD per ks
        for (int ks = 0; ks < ksteps; ks++) {
            uint32_t ah[2][4], al[2][4];
#pragma unroll
            for (int mt = 0; mt < 2; mt++) {
                int row = rowA + mt * 16;
                uint2 v0 = aptr[row];
                uint2 v1 = aptr[row + 8];
                uint2 v2 = aptr[4 * LDA_U + row];
                uint2 v3 = aptr[4 * LDA_U + row + 8];
                ah[mt][0] = v0.x; al[mt][0] = v0.y;
                ah[mt][1] = v1.x; al[mt][1] = v1.y;
                ah[mt][2] = v2.x; al[mt][2] = v2.y;
                ah[mt][3] = v3.x; al[mt][3] = v3.y;
            }
            uint4 b[8];
#pragma unroll
            for (int nt = 0; nt < 8; nt++) b[nt] = __ldg(wptr + nt * 8);
#pragma unroll
            for (int nt = 0; nt < 8; nt++)
#pragma unroll
                for (int mt = 0; mt < 2; mt++)
                    mma_bf16(c[mt][nt], ah[mt], b[nt].x, b[nt].z);   // hi*hi
#pragma unroll
            for (int nt = 0; nt < 8; nt++)
#pragma unroll
                for (int mt = 0; mt < 2; mt++)
                    mma_bf16(c[mt][nt], ah[mt], b[nt].y, b[nt].w);   // hi*lo
#pragma unroll
            for (int nt = 0; nt < 8; nt++)
#pragma unroll
                for (int mt = 0; mt < 2; mt++)
                    mma_bf16(c[mt][nt], al[mt], b[nt].x, b[nt].z);   // lo*hi
            aptr += 8 * LDA_U;
            wptr += 4 * HD;
        }
        __syncthreads();
    };

    auto write_act = [&](const float* sb) {
        uint2* An = (uint2*)sm;
#pragma unroll
        for (int mt = 0; mt < 2; mt++) {
            int row0 = rowA + mt * 16;
#pragma unroll
            for (int nt = 0; nt < 8; nt++) {
                int col = wn * 64 + nt * 8 + 2 * t;
                int p = wn * 32 + nt * 4 + t;
                float b0 = sb[col], b1 = sb[col + 1];
                An[p * LDA_U + row0]     = pack2(mishf(c[mt][nt][0] + b0), mishf(c[mt][nt][1] + b1));
                An[p * LDA_U + row0 + 8] = pack2(mishf(c[mt][nt][2] + b0), mishf(c[mt][nt][3] + b1));
            }
        }
        __syncthreads();
    };

    run_layer(wq1 + (size_t)e * 21 * 4 * HD, 21);
    write_act(sb1);
    run_layer(wq2 + (size_t)e * 16 * 4 * HD, 16);
    write_act(sb2);
    run_layer(wq3 + (size_t)e * 16 * 4 * HD, 16);

#pragma unroll
    for (int mt = 0; mt < 2; mt++) {
#pragma unroll
        for (int half = 0; half < 2; half++) {
            int m = wm * 32 + mt * 16 + half * 8 + g;
            int gi = base + m;
            if (gi < cnt) {
                int packed = srow[m];
                int row = packed & 0xFFFF, slot = packed >> 16;
                float w = swt[m];
                float* dst = g_eout + ((size_t)(row * 4 + slot)) * HD;
#pragma unroll
                for (int nt = 0; nt < 8; nt++) {
                    int col = wn * 64 + nt * 8 + 2 * t;
                    float2 o;
                    o.x = w * mishf(c[mt][nt][half * 2 + 0] + sb3[col]);
                    o.y = w * mishf(c[mt][nt][half * 2 + 1] + sb3[col + 1]);
                    *(float2*)&dst[col] = o;
                }
            }
        }
    }
}

// ---------------- kernel 4: combine slots + final linear + epilogue + aux ----------------
__global__ void __launch_bounds__(256, 1) final_kernel(
    const float* __restrict__ x, const float* __restrict__ fW,
    const float* __restrict__ fb, float* __restrict__ out, int out_size)
{
    extern __shared__ float smem[];
    float* cs  = smem;             // 32*260
    float* fWs = cs + 32 * 260;    // 256*64
    int tid = threadIdx.x;
    int base = blockIdx.x * 32;

    for (int i = tid; i < 4096; i += 256)
        ((float4*)fWs)[i] = ((const float4*)fW)[i];
    for (int idx = tid; idx < 32 * 64; idx += 256) {
        int m = idx >> 6, n4 = (idx & 63) << 2;
        size_t rb = ((size_t)(base + m)) * 4 * HD + n4;
        float4 a = *(const float4*)&g_eout[rb];
        float4 b = *(const float4*)&g_eout[rb + 256];
        float4 c = *(const float4*)&g_eout[rb + 512];
        float4 d = *(const float4*)&g_eout[rb + 768];
        float4 v;
        v.x = a.x + b.x + c.x + d.x;
        v.y = a.y + b.y + c.y + d.y;
        v.z = a.z + b.z + c.z + d.z;
        v.w = a.w + b.w + c.w + d.w;
        *(float4*)&cs[m * 260 + n4] = v;
    }
    __syncthreads();

    int ty = tid >> 4, tx = tid & 15;
    float acc[2][4];
#pragma unroll
    for (int mi = 0; mi < 2; mi++)
#pragma unroll
        for (int ci = 0; ci < 4; ci++) acc[mi][ci] = 0.f;
#pragma unroll 4
    for (int k = 0; k < 256; k++) {
        float4 b = *(const float4*)&fWs[k * 64 + (tx << 2)];
#pragma unroll
        for (int mi = 0; mi < 2; mi++) {
            float a = cs[(ty * 2 + mi) * 260 + k];
            acc[mi][0] = fmaf(a, b.x, acc[mi][0]);
            acc[mi][1] = fmaf(a, b.y, acc[mi][1]);
            acc[mi][2] = fmaf(a, b.z, acc[mi][2]);
            acc[mi][3] = fmaf(a, b.w, acc[mi][3]);
        }
    }
#pragma unroll
    for (int mi = 0; mi < 2; mi++) {
        int row = base + ty * 2 + mi;
        float co = g_cout[row], ck = g_cskip[row];
        float4 xr = *(const float4*)&x[row * 64 + (tx << 2)];
        float4 o;
        o.x = fminf(fmaxf(co * (acc[mi][0] + __ldg(&fb[(tx << 2) + 0])) + ck * xr.x, -1.f), 1.f);
        o.y = fminf(fmaxf(co * (acc[mi][1] + __ldg(&fb[(tx << 2) + 1])) + ck * xr.y, -1.f), 1.f);
        o.z = fminf(fmaxf(co * (acc[mi][2] + __ldg(&fb[(tx << 2) + 2])) + ck * xr.z, -1.f), 1.f);
        o.w = fminf(fmaxf(co * (acc[mi][3] + __ldg(&fb[(tx << 2) + 3])) + ck * xr.w, -1.f), 1.f);
        *(float4*)&out[row * 64 + (tx << 2)] = o;
    }

    // aux loss (fused)
    if (blockIdx.x == 0 && tid == 0 && out_size > NB * NACT) {
        float load[NE], mean = 0.f;
#pragma unroll
        for (int e = 0; e < NE; e++) { load[e] = (float)g_count[e] / (32768.0f + 1e-9f); mean += load[e]; }
        mean *= (1.0f / NE);
        float var = 0.f;
#pragma unroll
        for (int e = 0; e < NE; e++) { float d = load[e] - mean; var += d * d; }
        var *= (1.0f / (NE - 1));
        out[NB * NACT] = var + g_entropy / 32768.0f;
    }
}

extern "C" void kernel_launch(void* const* d_in, const int* in_sizes, int n_in,
                              void* d_out, int out_size)
{
    const float* x     = (const float*)d_in[0];
    const float* sigma = (const float*)d_in[1];
    const float* state = (const float*)d_in[2];
    const float* tW1 = (const float*)d_in[3];
    const float* tb1 = (const float*)d_in[4];
    const float* tW2 = (const float*)d_in[5];
    const float* tb2 = (const float*)d_in[6];
    const float* gW1 = (const float*)d_in[7];
    const float* gb1 = (const float*)d_in[8];
    const float* gW2 = (const float*)d_in[9];
    const float* gb2 = (const float*)d_in[10];
    const float* eW1 = (const float*)d_in[11];
    const float* eb1 = (const float*)d_in[12];
    const float* eW2 = (const float*)d_in[13];
    const float* eb2 = (const float*)d_in[14];
    const float* eW3 = (const float*)d_in[15];
    const float* eb3 = (const float*)d_in[16];
    const float* fW  = (const float*)d_in[17];
    const float* fb  = (const float*)d_in[18];
    float* out = (float*)d_out;

    const int gate1Smem = (32 * 340 + 2 * 32 * 256) * 4;          // 109056
    const int gate2Smem = (64 * 256 + 256 * 16 + 16) * 4;         // 81984
    const int finSmem   = (32 * 260 + 256 * 64 + 16) * 4;
    cudaFuncSetAttribute(gate1_kernel,  cudaFuncAttributeMaxDynamicSharedMemorySize, gate1Smem);
    cudaFuncSetAttribute(gate2_kernel,  cudaFuncAttributeMaxDynamicSharedMemorySize, gate2Smem);
    cudaFuncSetAttribute(expert_kernel, cudaFuncAttributeMaxDynamicSharedMemorySize, XSM_TOTAL);
    cudaFuncSetAttribute(final_kernel,  cudaFuncAttributeMaxDynamicSharedMemorySize, finSmem);

    prep_kernel<<<NB / 8, 256>>>(x, sigma, state, tW1, tb1, tW2, tb2);
    wconv_kernel<<<(NE * 21 * 4 * HD + 255) / 256, 256>>>(eW1, eW2, eW3);
    gate1_kernel<<<NB / 32, 256, gate1Smem>>>(gW1, gb1);
    gate2_kernel<<<NB / 64, 256, gate2Smem>>>(gW2, gb2);
    expert_kernel<<<dim3(NB / 64, NE), 256, XSM_TOTAL>>>(eb1, eb2, eb3);
    final_kernel<<<NB / 32, 256, finSmem>>>(x, fW, fb, out, out_size);
}

// round 15
// speedup vs baseline: 1.0929x; 1.0079x over previous
#include <cuda_runtime.h>
#include <cuda_bf16.h>
#include <math.h>
#include <stdint.h>

#define NB   32768
#define IND  336
#define HD   256
#define NE   16
#define NACT 64

// ---------------- device scratch ----------------
__device__ float g_inp[(size_t)NB * IND];
__device__ float g_g1[(size_t)NB * HD];         // gate layer-1 relu output
__device__ float g_cskip[NB];
__device__ float g_cout[NB];
__device__ int   g_count[NE];
__device__ float g_entropy;
__device__ int   g_bucket[NE * NB];             // row | slot<<16
__device__ float g_bw[NE * NB];
__device__ float g_eout[(size_t)NB * 4 * HD];   // per-(row,slot) weighted expert out

// packed weights [e][kstep][t][n]: uint4 = { pair(8ks+t): {hi,lo}, pair(8ks+t+4): {hi,lo} }
__device__ __align__(16) uint4 wq1[NE * 21 * 4 * HD];
__device__ __align__(16) uint4 wq2[NE * 16 * 4 * HD];
__device__ __align__(16) uint4 wq3[NE * 16 * 4 * HD];

__device__ __forceinline__ float mishf(float v) {
    if (v > 20.f) return v;
    float u = __expf(v);
    float w = 1.f + u;
    w = w * w;
    return v * __fdividef(w - 1.f, w + 1.f);
}

// ---------------- packing helpers ----------------
__device__ __forceinline__ uint2 pack2(float a, float b) {
    __nv_bfloat16 ha = __float2bfloat16_rn(a), hb = __float2bfloat16_rn(b);
    __nv_bfloat16 la = __float2bfloat16_rn(a - __bfloat162float(ha));
    __nv_bfloat16 lb = __float2bfloat16_rn(b - __bfloat162float(hb));
    uint2 r;
    r.x = (uint32_t)*(unsigned short*)&ha | ((uint32_t)*(unsigned short*)&hb << 16);
    r.y = (uint32_t)*(unsigned short*)&la | ((uint32_t)*(unsigned short*)&lb << 16);
    return r;
}

// ---------------- mma.sync (baseline PTX) ----------------
__device__ __forceinline__ void mma_bf16(float* c, const uint32_t* a, uint32_t b0, uint32_t b1) {
    asm volatile(
        "mma.sync.aligned.m16n8k16.row.col.f32.bf16.bf16.f32 "
        "{%0,%1,%2,%3}, {%4,%5,%6,%7}, {%8,%9}, {%0,%1,%2,%3};"
        : "+f"(c[0]), "+f"(c[1]), "+f"(c[2]), "+f"(c[3])
        : "r"(a[0]), "r"(a[1]), "r"(a[2]), "r"(a[3]), "r"(b0), "r"(b1));
}

// ---------------- packed fp32x2 FMA machinery (gate) ----------------
#define FMA2(d, a, b) asm("fma.rn.f32x2 %0, %1, %2, %0;" : "+l"(d) : "l"(a), "l"(b))
__device__ __forceinline__ unsigned long long dup2(float v) {
    unsigned long long r;
    asm("mov.b64 %0, {%1, %1};" : "=l"(r) : "r"(__float_as_uint(v)));
    return r;
}
__device__ __forceinline__ float2 unpack2(unsigned long long v) {
    float2 r;
    asm("mov.b64 {%0, %1}, %2;" : "=f"(r.x), "=f"(r.y) : "l"(v));
    return r;
}

// 32-row x 256-col FFMA2 GEMM; warp ty owns rows ty*4..+3; lane tx owns cols
// tx*4..+3 and 128+tx*4..+3. W tile double-buffered, one barrier per tile.
template<int LDA>
__device__ __forceinline__ void gemm32x256p(
    const float* __restrict__ A, int K,
    const float* __restrict__ Wg, float* __restrict__ Ws0, float* __restrict__ Ws1,
    unsigned long long (&acc)[4][4], int ty, int tx, int tid)
{
#pragma unroll
    for (int mi = 0; mi < 4; mi++)
#pragma unroll
        for (int ni = 0; ni < 4; ni++) acc[mi][ni] = 0ull;

    const float* Abase = A + ty * 4 * LDA;
    const int ntiles = (K + 31) >> 5;
    const int tx4 = tx << 2;

    float4 pf[8];
    int pr[8], pc[8];
#pragma unroll
    for (int i = 0; i < 8; i++) {
        int f4 = i * 256 + tid;
        pr[i] = f4 >> 6;
        pc[i] = (f4 & 63) << 2;
    }
#pragma unroll
    for (int i = 0; i < 8; i++) {
        int k = pr[i];
        pf[i] = (k < K) ? *(const float4*)&Wg[(size_t)k * 256 + pc[i]]
                        : make_float4(0.f, 0.f, 0.f, 0.f);
    }
    __syncthreads();

    for (int t = 0; t < ntiles; t++) {
        float* Ws = (t & 1) ? Ws1 : Ws0;
#pragma unroll
        for (int i = 0; i < 8; i++)
            *(float4*)&Ws[pr[i] * 256 + pc[i]] = pf[i];
        __syncthreads();
        if (t + 1 < ntiles) {
            int kt = (t + 1) << 5;
#pragma unroll
            for (int i = 0; i < 8; i++) {
                int k = kt + pr[i];
                pf[i] = (k < K) ? *(const float4*)&Wg[(size_t)k * 256 + pc[i]]
                                : make_float4(0.f, 0.f, 0.f, 0.f);
            }
        }
        int kt = t << 5;
        int kc = min(32, K - kt);
        const float* Ap = Abase + kt;
        for (int k = 0; k < kc; k += 2) {
            float2 a01[4];
#pragma unroll
            for (int mi = 0; mi < 4; mi++)
                a01[mi] = *(const float2*)&Ap[mi * LDA + k];
#pragma unroll
            for (int kk = 0; kk < 2; kk++) {
                const float* wrow = &Ws[(k + kk) * 256];
                ulonglong2 bb0 = *(const ulonglong2*)&wrow[tx4];
                ulonglong2 bb1 = *(const ulonglong2*)&wrow[128 + tx4];
#pragma unroll
                for (int mi = 0; mi < 4; mi++) {
                    unsigned long long a2 = dup2(kk ? a01[mi].y : a01[mi].x);
                    FMA2(acc[mi][0], a2, bb0.x);
                    FMA2(acc[mi][1], a2, bb0.y);
                    FMA2(acc[mi][2], a2, bb1.x);
                    FMA2(acc[mi][3], a2, bb1.y);
                }
            }
        }
    }
}

// ---------------- kernel 0: pack expert weights to [e][ks][t][n] uint4 ----------------
__global__ void wconv_kernel(const float* __restrict__ eW1, const float* __restrict__ eW2,
                             const float* __restrict__ eW3)
{
    int i = blockIdx.x * blockDim.x + threadIdx.x;
    if (i < NE * 21 * 4 * HD) {
        int n = i & 255; int r = i >> 8;
        int t = r & 3; int r2 = r >> 2;
        int ks = r2 % 21; int e = r2 / 21;
        int p0 = ks * 8 + t, p1 = p0 + 4;
        size_t k0 = ((size_t)e * IND + 2 * p0) * HD + n;
        size_t k1 = ((size_t)e * IND + 2 * p1) * HD + n;
        uint2 a = pack2(eW1[k0], eW1[k0 + HD]);
        uint2 b = pack2(eW1[k1], eW1[k1 + HD]);
        wq1[i] = make_uint4(a.x, a.y, b.x, b.y);
    }
    if (i < NE * 16 * 4 * HD) {
        int n = i & 255; int r = i >> 8;
        int t = r & 3; int r2 = r >> 2;
        int ks = r2 & 15; int e = r2 >> 4;
        int p0 = ks * 8 + t, p1 = p0 + 4;
        size_t k0 = ((size_t)e * HD + 2 * p0) * HD + n;
        size_t k1 = ((size_t)e * HD + 2 * p1) * HD + n;
        uint2 a2 = pack2(eW2[k0], eW2[k0 + HD]);
        uint2 b2 = pack2(eW2[k1], eW2[k1 + HD]);
        wq2[i] = make_uint4(a2.x, a2.y, b2.x, b2.y);
        uint2 a3 = pack2(eW3[k0], eW3[k0 + HD]);
        uint2 b3 = pack2(eW3[k1], eW3[k1 + HD]);
        wq3[i] = make_uint4(a3.x, a3.y, b3.x, b3.y);
    }
}

// ---------------- kernel 1: per-row prep ----------------
__global__ void prep_kernel(
    const float* __restrict__ x, const float* __restrict__ sigma,
    const float* __restrict__ state,
    const float* __restrict__ tW1, const float* __restrict__ tb1,
    const float* __restrict__ tW2, const float* __restrict__ tb2)
{
    if (blockIdx.x == 0 && threadIdx.x < NE) g_count[threadIdx.x] = 0;
    if (blockIdx.x == 0 && threadIdx.x == NE) g_entropy = 0.f;

    int wid  = (blockIdx.x * blockDim.x + threadIdx.x) >> 5;
    int lane = threadIdx.x & 31;
    if (wid >= NB) return;
    int r = wid;

    float sg  = __ldg(&sigma[r]);
    float sd2 = 0.25f;
    float d   = sg - 0.002f;
    float cskip = sd2 / (d * d + sd2);
    float inv = rsqrtf(sg * sg + sd2);
    float cout = d * 0.5f * inv;
    float cin  = inv;
    float rt   = 250.0f * logf(sg + 1e-44f);

    const float FR[8] = { 1.0f, 0.26826957952797246f, 0.07196856730011519f,
                          0.019306977288832496f, 0.005179474679231212f,
                          0.0013894954943731375f, 0.00037275937203149404f,
                          0.0001f };
    float pe[16];
#pragma unroll
    for (int i = 0; i < 8; i++) {
        float s, c;
        sincosf(rt * FR[i], &s, &c);
        pe[i] = s; pe[i + 8] = c;
    }
    float h1 = __ldg(&tb1[lane]);
#pragma unroll
    for (int i = 0; i < 16; i++) h1 = fmaf(pe[i], __ldg(&tW1[i * 32 + lane]), h1);
    {
        float sp = (h1 > 20.f) ? h1 : log1pf(expf(h1));
        h1 = h1 * tanhf(sp);
    }
    float tacc = (lane < 16) ? __ldg(&tb2[lane]) : 0.f;
#pragma unroll
    for (int j = 0; j < 32; j++) {
        float hj = __shfl_sync(0xffffffffu, h1, j);
        if (lane < 16) tacc = fmaf(hj, __ldg(&tW2[j * 16 + lane]), tacc);
    }
    float* row = g_inp + (size_t)r * IND;
    row[lane]      = cin * __ldg(&x[r * 64 + lane]);
    row[32 + lane] = cin * __ldg(&x[r * 64 + 32 + lane]);
    if (lane < 16) row[64 + lane] = tacc;
#pragma unroll
    for (int i = 0; i < 8; i++)
        row[80 + lane + i * 32] = __ldg(&state[r * 256 + lane + i * 32]);
    if (lane == 0) { g_cskip[r] = cskip; g_cout[r] = cout; }
}

// ---------------- kernel 2a: gate layer-1 GEMM (32 rows/block, 2 blocks/SM) ----------------
__global__ void __launch_bounds__(256, 2) gate1_kernel(
    const float* __restrict__ gW1, const float* __restrict__ gb1)
{
    extern __shared__ float smem[];
    float* Xs  = smem;              // 32*340
    float* Ws0 = Xs + 32 * 340;     // 32*256
    float* Ws1 = Ws0 + 32 * 256;    // 32*256

    int tid = threadIdx.x, ty = tid >> 5, tx = tid & 31;
    int base = blockIdx.x * 32;
    {
        int r = tid & 31, q = tid >> 5;   // 8 threads per row, 42 floats each
        const float* src = g_inp + (size_t)(base + r) * IND;
        for (int k = q * 42; k < q * 42 + 42; k++) Xs[r * 340 + k] = src[k];
    }
    unsigned long long acc[4][4];
    gemm32x256p<340>(Xs, IND, gW1, Ws0, Ws1, acc, ty, tx, tid);

    const int tx4 = tx << 2;
    float bs[8];
#pragma unroll
    for (int i = 0; i < 4; i++) { bs[i] = __ldg(&gb1[tx4 + i]); bs[4 + i] = __ldg(&gb1[128 + tx4 + i]); }
#pragma unroll
    for (int mi = 0; mi < 4; mi++) {
        float* o = g_g1 + (size_t)(base + ty * 4 + mi) * HD;
        float2 p0 = unpack2(acc[mi][0]);
        float2 p1 = unpack2(acc[mi][1]);
        float2 p2 = unpack2(acc[mi][2]);
        float2 p3 = unpack2(acc[mi][3]);
        float4 v0, v1;
        v0.x = fmaxf(p0.x + bs[0], 0.f); v0.y = fmaxf(p0.y + bs[1], 0.f);
        v0.z = fmaxf(p1.x + bs[2], 0.f); v0.w = fmaxf(p1.y + bs[3], 0.f);
        v1.x = fmaxf(p2.x + bs[4], 0.f); v1.y = fmaxf(p2.y + bs[5], 0.f);
        v1.z = fmaxf(p3.x + bs[6], 0.f); v1.w = fmaxf(p3.y + bs[7], 0.f);
        *(float4*)&o[tx4]       = v0;
        *(float4*)&o[128 + tx4] = v1;
    }
}

// ---------------- kernel 2b: gate layer-2 + softmax + top4 + routing ----------------
// W2 transposed in smem to [j][k] stride 260 (conflict-free float4 rows);
// 4 independent accumulators per dot product.
__global__ void __launch_bounds__(256, 2) gate2_kernel(
    const float* __restrict__ gW2, const float* __restrict__ gb2)
{
    extern __shared__ float smem[];
    float* G1s  = smem;             // 64*256
    float* W2t  = G1s + 64 * 256;   // 16*260 (transposed)
    float* entA = W2t + 16 * 260;   // 1

    int tid = threadIdx.x, ty = tid >> 5, tx = tid & 31;
    int base = blockIdx.x * 64;
    if (tid == 0) *entA = 0.f;
    for (int i = tid; i < 4096; i += 256)
        ((float4*)G1s)[i] = *(const float4*)&g_g1[(size_t)base * HD + i * 4];
    for (int i = tid; i < 4096; i += 256) {
        int k = i >> 4, j = i & 15;
        W2t[j * 260 + k] = gW2[k * 16 + j];
    }
    __syncthreads();

    int j = tx & 15, kh = tx >> 4;
    int k0 = kh * 128;
    const float* wrow = &W2t[j * 260 + k0];
    for (int rr = 0; rr < 8; rr++) {
        int m = ty * 8 + rr;
        int row = base + m;
        const float* g1 = &G1s[m * 256 + k0];
        float s0 = 0.f, s1 = 0.f, s2 = 0.f, s3 = 0.f;
#pragma unroll
        for (int k = 0; k < 128; k += 16) {
            float4 a0 = *(const float4*)&g1[k];
            float4 w0 = *(const float4*)&wrow[k];
            float4 a1 = *(const float4*)&g1[k + 4];
            float4 w1 = *(const float4*)&wrow[k + 4];
            float4 a2 = *(const float4*)&g1[k + 8];
            float4 w2 = *(const float4*)&wrow[k + 8];
            float4 a3 = *(const float4*)&g1[k + 12];
            float4 w3 = *(const float4*)&wrow[k + 12];
            s0 = fmaf(a0.x, w0.x, s0); s0 = fmaf(a0.y, w0.y, s0);
            s0 = fmaf(a0.z, w0.z, s0); s0 = fmaf(a0.w, w0.w, s0);
            s1 = fmaf(a1.x, w1.x, s1); s1 = fmaf(a1.y, w1.y, s1);
            s1 = fmaf(a1.z, w1.z, s1); s1 = fmaf(a1.w, w1.w, s1);
            s2 = fmaf(a2.x, w2.x, s2); s2 = fmaf(a2.y, w2.y, s2);
            s2 = fmaf(a2.z, w2.z, s2); s2 = fmaf(a2.w, w2.w, s2);
            s3 = fmaf(a3.x, w3.x, s3); s3 = fmaf(a3.y, w3.y, s3);
            s3 = fmaf(a3.z, w3.z, s3); s3 = fmaf(a3.w, w3.w, s3);
        }
        float s = (s0 + s1) + (s2 + s3);
        s += __shfl_down_sync(0xffffffffu, s, 16);
        float gv = s + __ldg(&gb2[j]);
        float p[16];
#pragma unroll
        for (int q = 0; q < 16; q++) p[q] = __shfl_sync(0xffffffffu, gv, q);
        float mx = p[0];
#pragma unroll
        for (int q = 1; q < 16; q++) mx = fmaxf(mx, p[q]);
        float Z = 0.f;
#pragma unroll
        for (int q = 0; q < 16; q++) { p[q] = expf(p[q] - mx); Z += p[q]; }
        float invZ = 1.f / Z;
        float ent = 0.f;
#pragma unroll
        for (int q = 0; q < 16; q++) { p[q] *= invZ; ent -= p[q] * logf(p[q] + 1e-9f); }
        unsigned usedm = 0;
        int   idx[4]; float val[4]; float wsum = 0.f;
#pragma unroll
        for (int s4 = 0; s4 < 4; s4++) {
            int best = 0; float bv = -1.f;
#pragma unroll
            for (int q = 0; q < 16; q++) {
                bool free = !((usedm >> q) & 1u);
                if (free && p[q] > bv) { bv = p[q]; best = q; }
            }
            usedm |= (1u << best);
            idx[s4] = best; val[s4] = bv; wsum += bv;
        }
        float invw = 1.f / (wsum + 1e-9f);
        if (tx < 4) {
            int ee = idx[tx];
            int pos = atomicAdd(&g_count[ee], 1);
            g_bucket[ee * NB + pos] = row | (tx << 16);
            g_bw[ee * NB + pos] = val[tx] * invw;
        }
        if (tx == 0) atomicAdd(entA, ent);
    }
    __syncthreads();
    if (tid == 0) atomicAdd(&g_entropy, *entA);
}

// ---------------- kernel 3: bf16-split HMMA expert MLP (R10 config) ----------------
#define LDA_U 68
#define XSM_META (168 * LDA_U * 8)        // 91392
#define XSM_TOTAL (XSM_META + 3584)

__global__ void __launch_bounds__(256, 2) expert_kernel(
    const float* __restrict__ eb1, const float* __restrict__ eb2,
    const float* __restrict__ eb3)
{
    extern __shared__ char sm[];
    int e = blockIdx.y;
    int cnt = g_count[e];
    int base = blockIdx.x * 64;
    if (base >= cnt) return;

    int tid = threadIdx.x;
    int lane = tid & 31, wid = tid >> 5;
    int wm = wid >> 2, wn = wid & 3;       // warp tile: rows [wm*32,+32), cols [wn*64,+64)
    int g = lane >> 2, t = lane & 3;

    int*   srow = (int*)(sm + XSM_META);
    float* swt  = (float*)(sm + XSM_META + 256);
    float* sb1  = (float*)(sm + XSM_META + 512);
    float* sb2  = (float*)(sm + XSM_META + 1536);
    float* sb3  = (float*)(sm + XSM_META + 2560);

    if (tid < 64) {
        int gi = base + tid;
        int gj = (gi < cnt) ? gi : (cnt - 1);
        srow[tid] = g_bucket[e * NB + gj];
        swt[tid]  = (gi < cnt) ? g_bw[e * NB + gj] : 0.f;
    }
    sb1[tid] = eb1[e * HD + tid];
    sb2[tid] = eb2[e * HD + tid];
    sb3[tid] = eb3[e * HD + tid];
    __syncthreads();

    {
        int r = tid & 63, q = tid >> 6;           // q in [0,4), 42 pairs each
        int rid = srow[r] & 0xFFFF;
        const float2* src = (const float2*)(g_inp + (size_t)rid * IND);
        uint2* A0 = (uint2*)sm;
        for (int p = q * 42; p < q * 42 + 42; p++) {
            float2 v = src[p];
            A0[p * LDA_U + r] = pack2(v.x, v.y);
        }
    }
    __syncthreads();

    float c[2][8][4];
    const int nbase = wn * 64 + g;
    const int rowA  = wm * 32 + g;

    auto run_layer = [&](const uint4* __restrict__ wq, int ksteps) {
#pragma unroll
        for (int a = 0; a < 2; a++)
#pragma unroll
            for (int b = 0; b < 8; b++)
#pragma unroll
                for (int d = 0; d < 4; d++) c[a][b][d] = 0.f;
        const uint2* aptr = (const uint2*)sm + t * LDA_U;
        const uint4* wptr = wq + (size_t)t * HD + nbase;
        for (int ks = 0; ks < ksteps; ks++) {
            uint32_t ah[2][4], al[2][4];
#pragma unroll
            for (int mt = 0; mt < 2; mt++) {
                int row = rowA + mt * 16;
                uint2 v0 = aptr[row];
                uint2 v1 = aptr[row + 8];
                uint2 v2 = aptr[4 * LDA_U + row];
                uint2 v3 = aptr[4 * LDA_U + row + 8];
                ah[mt][0] = v0.x; al[mt][0] = v0.y;
                ah[mt][1] = v1.x; al[mt][1] = v1.y;
                ah[mt][2] = v2.x; al[mt][2] = v2.y;
                ah[mt][3] = v3.x; al[mt][3] = v3.y;
            }
            uint4 b[8];
#pragma unroll
            for (int nt = 0; nt < 8; nt++) b[nt] = __ldg(wptr + nt * 8);
#pragma unroll
            for (int nt = 0; nt < 8; nt++)
#pragma unroll
                for (int mt = 0; mt < 2; mt++)
                    mma_bf16(c[mt][nt], ah[mt], b[nt].x, b[nt].z);   // hi*hi
#pragma unroll
            for (int nt = 0; nt < 8; nt++)
#pragma unroll
                for (int mt = 0; mt < 2; mt++)
                    mma_bf16(c[mt][nt], ah[mt], b[nt].y, b[nt].w);   // hi*lo
#pragma unroll
            for (int nt = 0; nt < 8; nt++)
#pragma unroll
                for (int mt = 0; mt < 2; mt++)
                    mma_bf16(c[mt][nt], al[mt], b[nt].x, b[nt].z);   // lo*hi
            aptr += 8 * LDA_U;
            wptr += 4 * HD;
        }
        __syncthreads();
    };

    auto write_act = [&](const float* sb) {
        uint2* An = (uint2*)sm;
#pragma unroll
        for (int mt = 0; mt < 2; mt++) {
            int row0 = rowA + mt * 16;
#pragma unroll
            for (int nt = 0; nt < 8; nt++) {
                int col = wn * 64 + nt * 8 + 2 * t;
                int p = wn * 32 + nt * 4 + t;
                float b0 = sb[col], b1 = sb[col + 1];
                An[p * LDA_U + row0]     = pack2(mishf(c[mt][nt][0] + b0), mishf(c[mt][nt][1] + b1));
                An[p * LDA_U + row0 + 8] = pack2(mishf(c[mt][nt][2] + b0), mishf(c[mt][nt][3] + b1));
            }
        }
        __syncthreads();
    };

    run_layer(wq1 + (size_t)e * 21 * 4 * HD, 21);
    write_act(sb1);
    run_layer(wq2 + (size_t)e * 16 * 4 * HD, 16);
    write_act(sb2);
    run_layer(wq3 + (size_t)e * 16 * 4 * HD, 16);

#pragma unroll
    for (int mt = 0; mt < 2; mt++) {
#pragma unroll
        for (int half = 0; half < 2; half++) {
            int m = wm * 32 + mt * 16 + half * 8 + g;
            int gi = base + m;
            if (gi < cnt) {
                int packed = srow[m];
                int row = packed & 0xFFFF, slot = packed >> 16;
                float w = swt[m];
                float* dst = g_eout + ((size_t)(row * 4 + slot)) * HD;
#pragma unroll
                for (int nt = 0; nt < 8; nt++) {
                    int col = wn * 64 + nt * 8 + 2 * t;
                    float2 o;
                    o.x = w * mishf(c[mt][nt][half * 2 + 0] + sb3[col]);
                    o.y = w * mishf(c[mt][nt][half * 2 + 1] + sb3[col + 1]);
                    *(float2*)&dst[col] = o;
                }
            }
        }
    }
}

// ---------------- kernel 4: combine slots + final linear + epilogue + aux ----------------
__global__ void __launch_bounds__(256, 2) final_kernel(
    const float* __restrict__ x, const float* __restrict__ fW,
    const float* __restrict__ fb, float* __restrict__ out, int out_size)
{
    extern __shared__ float smem[];
    float* cs  = smem;             // 32*260
    float* fWs = cs + 32 * 260;    // 256*64
    int tid = threadIdx.x;
    int base = blockIdx.x * 32;

    for (int i = tid; i < 4096; i += 256)
        ((float4*)fWs)[i] = ((const float4*)fW)[i];
    for (int idx = tid; idx < 32 * 64; idx += 256) {
        int m = idx >> 6, n4 = (idx & 63) << 2;
        size_t rb = ((size_t)(base + m)) * 4 * HD + n4;
        float4 a = *(const float4*)&g_eout[rb];
        float4 b = *(const float4*)&g_eout[rb + 256];
        float4 c = *(const float4*)&g_eout[rb + 512];
        float4 d = *(const float4*)&g_eout[rb + 768];
        float4 v;
        v.x = a.x + b.x + c.x + d.x;
        v.y = a.y + b.y + c.y + d.y;
        v.z = a.z + b.z + c.z + d.z;
        v.w = a.w + b.w + c.w + d.w;
        *(float4*)&cs[m * 260 + n4] = v;
    }
    __syncthreads();

    int ty = tid >> 4, tx = tid & 15;
    float acc[2][4];
#pragma unroll
    for (int mi = 0; mi < 2; mi++)
#pragma unroll
        for (int ci = 0; ci < 4; ci++) acc[mi][ci] = 0.f;
#pragma unroll 4
    for (int k = 0; k < 256; k++) {
        float4 b = *(const float4*)&fWs[k * 64 + (tx << 2)];
#pragma unroll
        for (int mi = 0; mi < 2; mi++) {
            float a = cs[(ty * 2 + mi) * 260 + k];
            acc[mi][0] = fmaf(a, b.x, acc[mi][0]);
            acc[mi][1] = fmaf(a, b.y, acc[mi][1]);
            acc[mi][2] = fmaf(a, b.z, acc[mi][2]);
            acc[mi][3] = fmaf(a, b.w, acc[mi][3]);
        }
    }
#pragma unroll
    for (int mi = 0; mi < 2; mi++) {
        int row = base + ty * 2 + mi;
        float co = g_cout[row], ck = g_cskip[row];
        float4 xr = *(const float4*)&x[row * 64 + (tx << 2)];
        float4 o;
        o.x = fminf(fmaxf(co * (acc[mi][0] + __ldg(&fb[(tx << 2) + 0])) + ck * xr.x, -1.f), 1.f);
        o.y = fminf(fmaxf(co * (acc[mi][1] + __ldg(&fb[(tx << 2) + 1])) + ck * xr.y, -1.f), 1.f);
        o.z = fminf(fmaxf(co * (acc[mi][2] + __ldg(&fb[(tx << 2) + 2])) + ck * xr.z, -1.f), 1.f);
        o.w = fminf(fmaxf(co * (acc[mi][3] + __ldg(&fb[(tx << 2) + 3])) + ck * xr.w, -1.f), 1.f);
        *(float4*)&out[row * 64 + (tx << 2)] = o;
    }

    // aux loss (fused)
    if (blockIdx.x == 0 && tid == 0 && out_size > NB * NACT) {
        float load[NE], mean = 0.f;
#pragma unroll
        for (int e = 0; e < NE; e++) { load[e] = (float)g_count[e] / (32768.0f + 1e-9f); mean += load[e]; }
        mean *= (1.0f / NE);
        float var = 0.f;
#pragma unroll
        for (int e = 0; e < NE; e++) { float d = load[e] - mean; var += d * d; }
        var *= (1.0f / (NE - 1));
        out[NB * NACT] = var + g_entropy / 32768.0f;
    }
}

extern "C" void kernel_launch(void* const* d_in, const int* in_sizes, int n_in,
                              void* d_out, int out_size)
{
    const float* x     = (const float*)d_in[0];
    const float* sigma = (const float*)d_in[1];
    const float* state = (const float*)d_in[2];
    const float* tW1 = (const float*)d_in[3];
    const float* tb1 = (const float*)d_in[4];
    const float* tW2 = (const float*)d_in[5];
    const float* tb2 = (const float*)d_in[6];
    const float* gW1 = (const float*)d_in[7];
    const float* gb1 = (const float*)d_in[8];
    const float* gW2 = (const float*)d_in[9];
    const float* gb2 = (const float*)d_in[10];
    const float* eW1 = (const float*)d_in[11];
    const float* eb1 = (const float*)d_in[12];
    const float* eW2 = (const float*)d_in[13];
    const float* eb2 = (const float*)d_in[14];
    const float* eW3 = (const float*)d_in[15];
    const float* eb3 = (const float*)d_in[16];
    const float* fW  = (const float*)d_in[17];
    const float* fb  = (const float*)d_in[18];
    float* out = (float*)d_out;

    const int gate1Smem = (32 * 340 + 2 * 32 * 256) * 4;          // 109056
    const int gate2Smem = (64 * 256 + 16 * 260 + 16) * 4;         // 82240
    const int finSmem   = (32 * 260 + 256 * 64 + 16) * 4;         // 98880
    cudaFuncSetAttribute(gate1_kernel,  cudaFuncAttributeMaxDynamicSharedMemorySize, gate1Smem);
    cudaFuncSetAttribute(gate2_kernel,  cudaFuncAttributeMaxDynamicSharedMemorySize, gate2Smem);
    cudaFuncSetAttribute(expert_kernel, cudaFuncAttributeMaxDynamicSharedMemorySize, XSM_TOTAL);
    cudaFuncSetAttribute(final_kernel,  cudaFuncAttributeMaxDynamicSharedMemorySize, finSmem);

    prep_kernel<<<NB / 8, 256>>>(x, sigma, state, tW1, tb1, tW2, tb2);
    wconv_kernel<<<(NE * 21 * 4 * HD + 255) / 256, 256>>>(eW1, eW2, eW3);
    gate1_kernel<<<NB / 32, 256, gate1Smem>>>(gW1, gb1);
    gate2_kernel<<<NB / 64, 256, gate2Smem>>>(gW2, gb2);
    expert_kernel<<<dim3(NB / 64, NE), 256, XSM_TOTAL>>>(eb1, eb2, eb3);
    final_kernel<<<NB / 32, 256, finSmem>>>(x, fW, fb, out, out_size);
}

// round 16
// speedup vs baseline: 1.1087x; 1.0145x over previous
#include <cuda_runtime.h>
#include <cuda_bf16.h>
#include <math.h>
#include <stdint.h>

#define NB   32768
#define IND  336
#define HD   256
#define NE   16
#define NACT 64

// ---------------- device scratch ----------------
__device__ float g_inp[(size_t)NB * IND];
__device__ float g_g1[(size_t)NB * HD];         // gate layer-1 relu output
__device__ float g_cskip[NB];
__device__ float g_cout[NB];
__device__ int   g_count[NE];
__device__ float g_entropy;
__device__ int   g_bucket[NE * NB];             // row | slot<<16
__device__ float g_bw[NE * NB];
__device__ float g_eout[(size_t)NB * 4 * HD];   // per-(row,slot) weighted expert out

// packed weights [e][kstep][t][n]: uint4 = { pair(8ks+t): {hi,lo}, pair(8ks+t+4): {hi,lo} }
__device__ __align__(16) uint4 wq1[NE * 21 * 4 * HD];
__device__ __align__(16) uint4 wq2[NE * 16 * 4 * HD];
__device__ __align__(16) uint4 wq3[NE * 16 * 4 * HD];

__device__ __forceinline__ float mishf(float v) {
    if (v > 20.f) return v;
    float u = __expf(v);
    float w = 1.f + u;
    w = w * w;
    return v * __fdividef(w - 1.f, w + 1.f);
}

// ---------------- packing helpers ----------------
__device__ __forceinline__ uint2 pack2(float a, float b) {
    __nv_bfloat16 ha = __float2bfloat16_rn(a), hb = __float2bfloat16_rn(b);
    __nv_bfloat16 la = __float2bfloat16_rn(a - __bfloat162float(ha));
    __nv_bfloat16 lb = __float2bfloat16_rn(b - __bfloat162float(hb));
    uint2 r;
    r.x = (uint32_t)*(unsigned short*)&ha | ((uint32_t)*(unsigned short*)&hb << 16);
    r.y = (uint32_t)*(unsigned short*)&la | ((uint32_t)*(unsigned short*)&lb << 16);
    return r;
}

// ---------------- mma.sync (baseline PTX) ----------------
__device__ __forceinline__ void mma_bf16(float* c, const uint32_t* a, uint32_t b0, uint32_t b1) {
    asm volatile(
        "mma.sync.aligned.m16n8k16.row.col.f32.bf16.bf16.f32 "
        "{%0,%1,%2,%3}, {%4,%5,%6,%7}, {%8,%9}, {%0,%1,%2,%3};"
        : "+f"(c[0]), "+f"(c[1]), "+f"(c[2]), "+f"(c[3])
        : "r"(a[0]), "r"(a[1]), "r"(a[2]), "r"(a[3]), "r"(b0), "r"(b1));
}

// ---------------- packed fp32x2 FMA machinery (gate) ----------------
#define FMA2(d, a, b) asm("fma.rn.f32x2 %0, %1, %2, %0;" : "+l"(d) : "l"(a), "l"(b))
__device__ __forceinline__ unsigned long long dup2(float v) {
    unsigned long long r;
    asm("mov.b64 %0, {%1, %1};" : "=l"(r) : "r"(__float_as_uint(v)));
    return r;
}
__device__ __forceinline__ float2 unpack2(unsigned long long v) {
    float2 r;
    asm("mov.b64 {%0, %1}, %2;" : "=f"(r.x), "=f"(r.y) : "l"(v));
    return r;
}

// 32-row x 256-col FFMA2 GEMM; warp ty owns rows ty*4..+3; lane tx owns cols
// tx*4..+3 and 128+tx*4..+3. W tile double-buffered, one barrier per tile.
template<int LDA>
__device__ __forceinline__ void gemm32x256p(
    const float* __restrict__ A, int K,
    const float* __restrict__ Wg, float* __restrict__ Ws0, float* __restrict__ Ws1,
    unsigned long long (&acc)[4][4], int ty, int tx, int tid)
{
#pragma unroll
    for (int mi = 0; mi < 4; mi++)
#pragma unroll
        for (int ni = 0; ni < 4; ni++) acc[mi][ni] = 0ull;

    const float* Abase = A + ty * 4 * LDA;
    const int ntiles = (K + 31) >> 5;
    const int tx4 = tx << 2;

    float4 pf[8];
    int pr[8], pc[8];
#pragma unroll
    for (int i = 0; i < 8; i++) {
        int f4 = i * 256 + tid;
        pr[i] = f4 >> 6;
        pc[i] = (f4 & 63) << 2;
    }
#pragma unroll
    for (int i = 0; i < 8; i++) {
        int k = pr[i];
        pf[i] = (k < K) ? *(const float4*)&Wg[(size_t)k * 256 + pc[i]]
                        : make_float4(0.f, 0.f, 0.f, 0.f);
    }
    __syncthreads();

    for (int t = 0; t < ntiles; t++) {
        float* Ws = (t & 1) ? Ws1 : Ws0;
#pragma unroll
        for (int i = 0; i < 8; i++)
            *(float4*)&Ws[pr[i] * 256 + pc[i]] = pf[i];
        __syncthreads();
        if (t + 1 < ntiles) {
            int kt = (t + 1) << 5;
#pragma unroll
            for (int i = 0; i < 8; i++) {
                int k = kt + pr[i];
                pf[i] = (k < K) ? *(const float4*)&Wg[(size_t)k * 256 + pc[i]]
                                : make_float4(0.f, 0.f, 0.f, 0.f);
            }
        }
        int kt = t << 5;
        int kc = min(32, K - kt);
        const float* Ap = Abase + kt;
        for (int k = 0; k < kc; k += 2) {
            float2 a01[4];
#pragma unroll
            for (int mi = 0; mi < 4; mi++)
                a01[mi] = *(const float2*)&Ap[mi * LDA + k];
#pragma unroll
            for (int kk = 0; kk < 2; kk++) {
                const float* wrow = &Ws[(k + kk) * 256];
                ulonglong2 bb0 = *(const ulonglong2*)&wrow[tx4];
                ulonglong2 bb1 = *(const ulonglong2*)&wrow[128 + tx4];
#pragma unroll
                for (int mi = 0; mi < 4; mi++) {
                    unsigned long long a2 = dup2(kk ? a01[mi].y : a01[mi].x);
                    FMA2(acc[mi][0], a2, bb0.x);
                    FMA2(acc[mi][1], a2, bb0.y);
                    FMA2(acc[mi][2], a2, bb1.x);
                    FMA2(acc[mi][3], a2, bb1.y);
                }
            }
        }
    }
}

// ---------------- kernel 1: per-row prep (+ fused weight packing blocks) ----------------
#define PREP_BLOCKS (NB / 8)
#define WCONV_BLOCKS ((NE * 21 * 4 * HD + 255) / 256)

__global__ void prep_kernel(
    const float* __restrict__ x, const float* __restrict__ sigma,
    const float* __restrict__ state,
    const float* __restrict__ tW1, const float* __restrict__ tb1,
    const float* __restrict__ tW2, const float* __restrict__ tb2,
    const float* __restrict__ eW1, const float* __restrict__ eW2,
    const float* __restrict__ eW3)
{
    if (blockIdx.x >= PREP_BLOCKS) {
        // ---- fused wconv: pack expert weights to [e][ks][t][n] uint4 ----
        int i = (blockIdx.x - PREP_BLOCKS) * blockDim.x + threadIdx.x;
        if (i < NE * 21 * 4 * HD) {
            int n = i & 255; int r = i >> 8;
            int t = r & 3; int r2 = r >> 2;
            int ks = r2 % 21; int e = r2 / 21;
            int p0 = ks * 8 + t, p1 = p0 + 4;
            size_t k0 = ((size_t)e * IND + 2 * p0) * HD + n;
            size_t k1 = ((size_t)e * IND + 2 * p1) * HD + n;
            uint2 a = pack2(eW1[k0], eW1[k0 + HD]);
            uint2 b = pack2(eW1[k1], eW1[k1 + HD]);
            wq1[i] = make_uint4(a.x, a.y, b.x, b.y);
        }
        if (i < NE * 16 * 4 * HD) {
            int n = i & 255; int r = i >> 8;
            int t = r & 3; int r2 = r >> 2;
            int ks = r2 & 15; int e = r2 >> 4;
            int p0 = ks * 8 + t, p1 = p0 + 4;
            size_t k0 = ((size_t)e * HD + 2 * p0) * HD + n;
            size_t k1 = ((size_t)e * HD + 2 * p1) * HD + n;
            uint2 a2 = pack2(eW2[k0], eW2[k0 + HD]);
            uint2 b2 = pack2(eW2[k1], eW2[k1 + HD]);
            wq2[i] = make_uint4(a2.x, a2.y, b2.x, b2.y);
            uint2 a3 = pack2(eW3[k0], eW3[k0 + HD]);
            uint2 b3 = pack2(eW3[k1], eW3[k1 + HD]);
            wq3[i] = make_uint4(a3.x, a3.y, b3.x, b3.y);
        }
        return;
    }

    if (blockIdx.x == 0 && threadIdx.x < NE) g_count[threadIdx.x] = 0;
    if (blockIdx.x == 0 && threadIdx.x == NE) g_entropy = 0.f;

    int wid  = (blockIdx.x * blockDim.x + threadIdx.x) >> 5;
    int lane = threadIdx.x & 31;
    int r = wid;

    float sg  = __ldg(&sigma[r]);
    float sd2 = 0.25f;
    float d   = sg - 0.002f;
    float cskip = sd2 / (d * d + sd2);
    float inv = rsqrtf(sg * sg + sd2);
    float cout = d * 0.5f * inv;
    float cin  = inv;
    float rt   = 250.0f * logf(sg + 1e-44f);

    const float FR[8] = { 1.0f, 0.26826957952797246f, 0.07196856730011519f,
                          0.019306977288832496f, 0.005179474679231212f,
                          0.0013894954943731375f, 0.00037275937203149404f,
                          0.0001f };
    float pe[16];
#pragma unroll
    for (int i = 0; i < 8; i++) {
        float s, c;
        sincosf(rt * FR[i], &s, &c);
        pe[i] = s; pe[i + 8] = c;
    }
    float h1 = __ldg(&tb1[lane]);
#pragma unroll
    for (int i = 0; i < 16; i++) h1 = fmaf(pe[i], __ldg(&tW1[i * 32 + lane]), h1);
    {
        float sp = (h1 > 20.f) ? h1 : log1pf(expf(h1));
        h1 = h1 * tanhf(sp);
    }
    float tacc = (lane < 16) ? __ldg(&tb2[lane]) : 0.f;
#pragma unroll
    for (int j = 0; j < 32; j++) {
        float hj = __shfl_sync(0xffffffffu, h1, j);
        if (lane < 16) tacc = fmaf(hj, __ldg(&tW2[j * 16 + lane]), tacc);
    }
    float* row = g_inp + (size_t)r * IND;
    row[lane]      = cin * __ldg(&x[r * 64 + lane]);
    row[32 + lane] = cin * __ldg(&x[r * 64 + 32 + lane]);
    if (lane < 16) row[64 + lane] = tacc;
#pragma unroll
    for (int i = 0; i < 8; i++)
        row[80 + lane + i * 32] = __ldg(&state[r * 256 + lane + i * 32]);
    if (lane == 0) { g_cskip[r] = cskip; g_cout[r] = cout; }
}

// ---------------- kernel 2a: gate layer-1 GEMM (32 rows/block, 2 blocks/SM) ----------------
__global__ void __launch_bounds__(256, 2) gate1_kernel(
    const float* __restrict__ gW1, const float* __restrict__ gb1)
{
    extern __shared__ float smem[];
    float* Xs  = smem;              // 32*340
    float* Ws0 = Xs + 32 * 340;     // 32*256
    float* Ws1 = Ws0 + 32 * 256;    // 32*256

    int tid = threadIdx.x, ty = tid >> 5, tx = tid & 31;
    int base = blockIdx.x * 32;
    {
        int r = tid & 31, q = tid >> 5;   // 8 threads per row, 42 floats each
        const float* src = g_inp + (size_t)(base + r) * IND;
        for (int k = q * 42; k < q * 42 + 42; k++) Xs[r * 340 + k] = src[k];
    }
    unsigned long long acc[4][4];
    gemm32x256p<340>(Xs, IND, gW1, Ws0, Ws1, acc, ty, tx, tid);

    const int tx4 = tx << 2;
    float bs[8];
#pragma unroll
    for (int i = 0; i < 4; i++) { bs[i] = __ldg(&gb1[tx4 + i]); bs[4 + i] = __ldg(&gb1[128 + tx4 + i]); }
#pragma unroll
    for (int mi = 0; mi < 4; mi++) {
        float* o = g_g1 + (size_t)(base + ty * 4 + mi) * HD;
        float2 p0 = unpack2(acc[mi][0]);
        float2 p1 = unpack2(acc[mi][1]);
        float2 p2 = unpack2(acc[mi][2]);
        float2 p3 = unpack2(acc[mi][3]);
        float4 v0, v1;
        v0.x = fmaxf(p0.x + bs[0], 0.f); v0.y = fmaxf(p0.y + bs[1], 0.f);
        v0.z = fmaxf(p1.x + bs[2], 0.f); v0.w = fmaxf(p1.y + bs[3], 0.f);
        v1.x = fmaxf(p2.x + bs[4], 0.f); v1.y = fmaxf(p2.y + bs[5], 0.f);
        v1.z = fmaxf(p3.x + bs[6], 0.f); v1.w = fmaxf(p3.y + bs[7], 0.f);
        *(float4*)&o[tx4]       = v0;
        *(float4*)&o[128 + tx4] = v1;
    }
}

// ---------------- kernel 2b: gate layer-2 + softmax + top4 + routing ----------------
// Half-warp per row: lanes [0,16) handle one row, [16,32) another. Each 16-lane
// group computes a full 256-k dot (4 indep accumulators, no cross-half reduce),
// then runs softmax/top4 for its own row -> serial tail executes 4x per warp.
__global__ void __launch_bounds__(256, 2) gate2_kernel(
    const float* __restrict__ gW2, const float* __restrict__ gb2)
{
    extern __shared__ float smem[];
    float* G1s  = smem;             // 64*256
    float* W2t  = G1s + 64 * 256;   // 16*260 (transposed)
    float* entA = W2t + 16 * 260;   // 1

    int tid = threadIdx.x, ty = tid >> 5, tx = tid & 31;
    int base = blockIdx.x * 64;
    if (tid == 0) *entA = 0.f;
    for (int i = tid; i < 4096; i += 256)
        ((float4*)G1s)[i] = *(const float4*)&g_g1[(size_t)base * HD + i * 4];
    for (int i = tid; i < 4096; i += 256) {
        int k = i >> 4, j = i & 15;
        W2t[j * 260 + k] = gW2[k * 16 + j];
    }
    __syncthreads();

    int j = tx & 15, h = tx >> 4;
    const float* wrow = &W2t[j * 260];
    for (int rr = 0; rr < 4; rr++) {
        int m = ty * 8 + rr * 2 + h;
        int row = base + m;
        const float* g1 = &G1s[m * 256];
        float s0 = 0.f, s1 = 0.f, s2 = 0.f, s3 = 0.f;
#pragma unroll
        for (int k = 0; k < 256; k += 16) {
            float4 a0 = *(const float4*)&g1[k];
            float4 w0 = *(const float4*)&wrow[k];
            float4 a1 = *(const float4*)&g1[k + 4];
            float4 w1 = *(const float4*)&wrow[k + 4];
            float4 a2 = *(const float4*)&g1[k + 8];
            float4 w2 = *(const float4*)&wrow[k + 8];
            float4 a3 = *(const float4*)&g1[k + 12];
            float4 w3 = *(const float4*)&wrow[k + 12];
            s0 = fmaf(a0.x, w0.x, s0); s0 = fmaf(a0.y, w0.y, s0);
            s0 = fmaf(a0.z, w0.z, s0); s0 = fmaf(a0.w, w0.w, s0);
            s1 = fmaf(a1.x, w1.x, s1); s1 = fmaf(a1.y, w1.y, s1);
            s1 = fmaf(a1.z, w1.z, s1); s1 = fmaf(a1.w, w1.w, s1);
            s2 = fmaf(a2.x, w2.x, s2); s2 = fmaf(a2.y, w2.y, s2);
            s2 = fmaf(a2.z, w2.z, s2); s2 = fmaf(a2.w, w2.w, s2);
            s3 = fmaf(a3.x, w3.x, s3); s3 = fmaf(a3.y, w3.y, s3);
            s3 = fmaf(a3.z, w3.z, s3); s3 = fmaf(a3.w, w3.w, s3);
        }
        float gv = (s0 + s1) + (s2 + s3) + __ldg(&gb2[j]);
        float p[16];
#pragma unroll
        for (int q = 0; q < 16; q++) p[q] = __shfl_sync(0xffffffffu, gv, q, 16);
        float mx = p[0];
#pragma unroll
        for (int q = 1; q < 16; q++) mx = fmaxf(mx, p[q]);
        float Z = 0.f;
#pragma unroll
        for (int q = 0; q < 16; q++) { p[q] = expf(p[q] - mx); Z += p[q]; }
        float invZ = 1.f / Z;
        float ent = 0.f;
#pragma unroll
        for (int q = 0; q < 16; q++) { p[q] *= invZ; ent -= p[q] * logf(p[q] + 1e-9f); }
        unsigned usedm = 0;
        int   idx[4]; float val[4]; float wsum = 0.f;
#pragma unroll
        for (int s4 = 0; s4 < 4; s4++) {
            int best = 0; float bv = -1.f;
#pragma unroll
            for (int q = 0; q < 16; q++) {
                bool free = !((usedm >> q) & 1u);
                if (free && p[q] > bv) { bv = p[q]; best = q; }
            }
            usedm |= (1u << best);
            idx[s4] = best; val[s4] = bv; wsum += bv;
        }
        float invw = 1.f / (wsum + 1e-9f);
        if (j < 4) {
            int ee = idx[j];
            int pos = atomicAdd(&g_count[ee], 1);
            g_bucket[ee * NB + pos] = row | (j << 16);
            g_bw[ee * NB + pos] = val[j] * invw;
        }
        if (j == 0) atomicAdd(entA, ent);
    }
    __syncthreads();
    if (tid == 0) atomicAdd(&g_entropy, *entA);
}

// ---------------- kernel 3: bf16-split HMMA expert MLP (R10 config) ----------------
#define LDA_U 68
#define XSM_META (168 * LDA_U * 8)        // 91392
#define XSM_TOTAL (XSM_META + 3584)

__global__ void __launch_bounds__(256, 2) expert_kernel(
    const float* __restrict__ eb1, const float* __restrict__ eb2,
    const float* __restrict__ eb3)
{
    extern __shared__ char sm[];
    int e = blockIdx.y;
    int cnt = g_count[e];
    int base = blockIdx.x * 64;
    if (base >= cnt) return;

    int tid = threadIdx.x;
    int lane = tid & 31, wid = tid >> 5;
    int wm = wid >> 2, wn = wid & 3;       // warp tile: rows [wm*32,+32), cols [wn*64,+64)
    int g = lane >> 2, t = lane & 3;

    int*   srow = (int*)(sm + XSM_META);
    float* swt  = (float*)(sm + XSM_META + 256);
    float* sb1  = (float*)(sm + XSM_META + 512);
    float* sb2  = (float*)(sm + XSM_META + 1536);
    float* sb3  = (float*)(sm + XSM_META + 2560);

    if (tid < 64) {
        int gi = base + tid;
        int gj = (gi < cnt) ? gi : (cnt - 1);
        srow[tid] = g_bucket[e * NB + gj];
        swt[tid]  = (gi < cnt) ? g_bw[e * NB + gj] : 0.f;
    }
    sb1[tid] = eb1[e * HD + tid];
    sb2[tid] = eb2[e * HD + tid];
    sb3[tid] = eb3[e * HD + tid];
    __syncthreads();

    {
        int r = tid & 63, q = tid >> 6;           // q in [0,4), 42 pairs each
        int rid = srow[r] & 0xFFFF;
        const float2* src = (const float2*)(g_inp + (size_t)rid * IND);
        uint2* A0 = (uint2*)sm;
        for (int p = q * 42; p < q * 42 + 42; p++) {
            float2 v = src[p];
            A0[p * LDA_U + r] = pack2(v.x, v.y);
        }
    }
    __syncthreads();

    float c[2][8][4];
    const int nbase = wn * 64 + g;
    const int rowA  = wm * 32 + g;

    auto run_layer = [&](const uint4* __restrict__ wq, int ksteps) {
#pragma unroll
        for (int a = 0; a < 2; a++)
#pragma unroll
            for (int b = 0; b < 8; b++)
#pragma unroll
                for (int d = 0; d < 4; d++) c[a][b][d] = 0.f;
        const uint2* aptr = (const uint2*)sm + t * LDA_U;
        const uint4* wptr = wq + (size_t)t * HD + nbase;
        for (int ks = 0; ks < ksteps; ks++) {
            uint32_t ah[2][4], al[2][4];
#pragma unroll
            for (int mt = 0; mt < 2; mt++) {
                int row = rowA + mt * 16;
                uint2 v0 = aptr[row];
                uint2 v1 = aptr[row + 8];
                uint2 v2 = aptr[4 * LDA_U + row];
                uint2 v3 = aptr[4 * LDA_U + row + 8];
                ah[mt][0] = v0.x; al[mt][0] = v0.y;
                ah[mt][1] = v1.x; al[mt][1] = v1.y;
                ah[mt][2] = v2.x; al[mt][2] = v2.y;
                ah[mt][3] = v3.x; al[mt][3] = v3.y;
            }
            uint4 b[8];
#pragma unroll
            for (int nt = 0; nt < 8; nt++) b[nt] = __ldg(wptr + nt * 8);
#pragma unroll
            for (int nt = 0; nt < 8; nt++)
#pragma unroll
                for (int mt = 0; mt < 2; mt++)
                    mma_bf16(c[mt][nt], ah[mt], b[nt].x, b[nt].z);   // hi*hi
#pragma unroll
            for (int nt = 0; nt < 8; nt++)
#pragma unroll
                for (int mt = 0; mt < 2; mt++)
                    mma_bf16(c[mt][nt], ah[mt], b[nt].y, b[nt].w);   // hi*lo
#pragma unroll
            for (int nt = 0; nt < 8; nt++)
#pragma unroll
                for (int mt = 0; mt < 2; mt++)
                    mma_bf16(c[mt][nt], al[mt], b[nt].x, b[nt].z);   // lo*hi
            aptr += 8 * LDA_U;
            wptr += 4 * HD;
        }
        __syncthreads();
    };

    auto write_act = [&](const float* sb) {
        uint2* An = (uint2*)sm;
#pragma unroll
        for (int mt = 0; mt < 2; mt++) {
            int row0 = rowA + mt * 16;
#pragma unroll
            for (int nt = 0; nt < 8; nt++) {
                int col = wn * 64 + nt * 8 + 2 * t;
                int p = wn * 32 + nt * 4 + t;
                float b0 = sb[col], b1 = sb[col + 1];
                An[p * LDA_U + row0]     = pack2(mishf(c[mt][nt][0] + b0), mishf(c[mt][nt][1] + b1));
                An[p * LDA_U + row0 + 8] = pack2(mishf(c[mt][nt][2] + b0), mishf(c[mt][nt][3] + b1));
            }
        }
        __syncthreads();
    };

    run_layer(wq1 + (size_t)e * 21 * 4 * HD, 21);
    write_act(sb1);
    run_layer(wq2 + (size_t)e * 16 * 4 * HD, 16);
    write_act(sb2);
    run_layer(wq3 + (size_t)e * 16 * 4 * HD, 16);

#pragma unroll
    for (int mt = 0; mt < 2; mt++) {
#pragma unroll
        for (int half = 0; half < 2; half++) {
            int m = wm * 32 + mt * 16 + half * 8 + g;
            int gi = base + m;
            if (gi < cnt) {
                int packed = srow[m];
                int row = packed & 0xFFFF, slot = packed >> 16;
                float w = swt[m];
                float* dst = g_eout + ((size_t)(row * 4 + slot)) * HD;
#pragma unroll
                for (int nt = 0; nt < 8; nt++) {
                    int col = wn * 64 + nt * 8 + 2 * t;
                    float2 o;
                    o.x = w * mishf(c[mt][nt][half * 2 + 0] + sb3[col]);
                    o.y = w * mishf(c[mt][nt][half * 2 + 1] + sb3[col + 1]);
                    *(float2*)&dst[col] = o;
                }
            }
        }
    }
}

// ---------------- kernel 4: combine slots + final linear + epilogue + aux ----------------
__global__ void __launch_bounds__(256, 2) final_kernel(
    const float* __restrict__ x, const float* __restrict__ fW,
    const float* __restrict__ fb, float* __restrict__ out, int out_size)
{
    extern __shared__ float smem[];
    float* cs  = smem;             // 32*260
    float* fWs = cs + 32 * 260;    // 256*64
    int tid = threadIdx.x;
    int base = blockIdx.x * 32;

    for (int i = tid; i < 4096; i += 256)
        ((float4*)fWs)[i] = ((const float4*)fW)[i];
    for (int idx = tid; idx < 32 * 64; idx += 256) {
        int m = idx >> 6, n4 = (idx & 63) << 2;
        size_t rb = ((size_t)(base + m)) * 4 * HD + n4;
        float4 a = *(const float4*)&g_eout[rb];
        float4 b = *(const float4*)&g_eout[rb + 256];
        float4 c = *(const float4*)&g_eout[rb + 512];
        float4 d = *(const float4*)&g_eout[rb + 768];
        float4 v;
        v.x = a.x + b.x + c.x + d.x;
        v.y = a.y + b.y + c.y + d.y;
        v.z = a.z + b.z + c.z + d.z;
        v.w = a.w + b.w + c.w + d.w;
        *(float4*)&cs[m * 260 + n4] = v;
    }
    __syncthreads();

    int ty = tid >> 4, tx = tid & 15;
    float acc[2][4];
#pragma unroll
    for (int mi = 0; mi < 2; mi++)
#pragma unroll
        for (int ci = 0; ci < 4; ci++) acc[mi][ci] = 0.f;
#pragma unroll 4
    for (int k = 0; k < 256; k++) {
        float4 b = *(const float4*)&fWs[k * 64 + (tx << 2)];
#pragma unroll
        for (int mi = 0; mi < 2; mi++) {
            float a = cs[(ty * 2 + mi) * 260 + k];
            acc[mi][0] = fmaf(a, b.x, acc[mi][0]);
            acc[mi][1] = fmaf(a, b.y, acc[mi][1]);
            acc[mi][2] = fmaf(a, b.z, acc[mi][2]);
            acc[mi][3] = fmaf(a, b.w, acc[mi][3]);
        }
    }
#pragma unroll
    for (int mi = 0; mi < 2; mi++) {
        int row = base + ty * 2 + mi;
        float co = g_cout[row], ck = g_cskip[row];
        float4 xr = *(const float4*)&x[row * 64 + (tx << 2)];
        float4 o;
        o.x = fminf(fmaxf(co * (acc[mi][0] + __ldg(&fb[(tx << 2) + 0])) + ck * xr.x, -1.f), 1.f);
        o.y = fminf(fmaxf(co * (acc[mi][1] + __ldg(&fb[(tx << 2) + 1])) + ck * xr.y, -1.f), 1.f);
        o.z = fminf(fmaxf(co * (acc[mi][2] + __ldg(&fb[(tx << 2) + 2])) + ck * xr.z, -1.f), 1.f);
        o.w = fminf(fmaxf(co * (acc[mi][3] + __ldg(&fb[(tx << 2) + 3])) + ck * xr.w, -1.f), 1.f);
        *(float4*)&out[row * 64 + (tx << 2)] = o;
    }

    // aux loss (fused)
    if (blockIdx.x == 0 && tid == 0 && out_size > NB * NACT) {
        float load[NE], mean = 0.f;
#pragma unroll
        for (int e = 0; e < NE; e++) { load[e] = (float)g_count[e] / (32768.0f + 1e-9f); mean += load[e]; }
        mean *= (1.0f / NE);
        float var = 0.f;
#pragma unroll
        for (int e = 0; e < NE; e++) { float d = load[e] - mean; var += d * d; }
        var *= (1.0f / (NE - 1));
        out[NB * NACT] = var + g_entropy / 32768.0f;
    }
}

extern "C" void kernel_launch(void* const* d_in, const int* in_sizes, int n_in,
                              void* d_out, int out_size)
{
    const float* x     = (const float*)d_in[0];
    const float* sigma = (const float*)d_in[1];
    const float* state = (const float*)d_in[2];
    const float* tW1 = (const float*)d_in[3];
    const float* tb1 = (const float*)d_in[4];
    const float* tW2 = (const float*)d_in[5];
    const float* tb2 = (const float*)d_in[6];
    const float* gW1 = (const float*)d_in[7];
    const float* gb1 = (const float*)d_in[8];
    const float* gW2 = (const float*)d_in[9];
    const float* gb2 = (const float*)d_in[10];
    const float* eW1 = (const float*)d_in[11];
    const float* eb1 = (const float*)d_in[12];
    const float* eW2 = (const float*)d_in[13];
    const float* eb2 = (const float*)d_in[14];
    const float* eW3 = (const float*)d_in[15];
    const float* eb3 = (const float*)d_in[16];
    const float* fW  = (const float*)d_in[17];
    const float* fb  = (const float*)d_in[18];
    float* out = (float*)d_out;

    const int gate1Smem = (32 * 340 + 2 * 32 * 256) * 4;          // 109056
    const int gate2Smem = (64 * 256 + 16 * 260 + 16) * 4;         // 82240
    const int finSmem   = (32 * 260 + 256 * 64 + 16) * 4;         // 98880
    cudaFuncSetAttribute(gate1_kernel,  cudaFuncAttributeMaxDynamicSharedMemorySize, gate1Smem);
    cudaFuncSetAttribute(gate2_kernel,  cudaFuncAttributeMaxDynamicSharedMemorySize, gate2Smem);
    cudaFuncSetAttribute(expert_kernel, cudaFuncAttributeMaxDynamicSharedMemorySize, XSM_TOTAL);
    cudaFuncSetAttribute(final_kernel,  cudaFuncAttributeMaxDynamicSharedMemorySize, finSmem);

    prep_kernel<<<PREP_BLOCKS + WCONV_BLOCKS, 256>>>(
        x, sigma, state, tW1, tb1, tW2, tb2, eW1, eW2, eW3);
    gate1_kernel<<<NB / 32, 256, gate1Smem>>>(gW1, gb1);
    gate2_kernel<<<NB / 64, 256, gate2Smem>>>(gW2, gb2);
    expert_kernel<<<dim3(NB / 64, NE), 256, XSM_TOTAL>>>(eb1, eb2, eb3);
    final_kernel<<<NB / 32, 256, finSmem>>>(x, fW, fb, out, out_size);
}

// round 17
// speedup vs baseline: 1.2216x; 1.1018x over previous
#include <cuda_runtime.h>
#include <cuda_bf16.h>
#include <math.h>
#include <stdint.h>

#define NB   32768
#define IND  336
#define HD   256
#define NE   16
#define NACT 64

// ---------------- device scratch ----------------
__device__ float g_inp[(size_t)NB * IND];
__device__ float g_g1[(size_t)NB * HD];         // gate layer-1 relu output
__device__ float g_cskip[NB];
__device__ float g_cout[NB];
__device__ int   g_count[NE];
__device__ float g_entropy;
__device__ int   g_bucket[NE * NB];             // row | slot<<16
__device__ float g_bw[NE * NB];
__device__ float g_eout[(size_t)NB * 4 * HD];   // per-(row,slot) weighted expert out

// packed weights [e][kstep][t][n]: uint4 = { pair(8ks+t): {hi,lo}, pair(8ks+t+4): {hi,lo} }
// wq1 has NE+1 slots: slot NE = gate W1 (same [336,256] shape)
__device__ __align__(16) uint4 wq1[(NE + 1) * 21 * 4 * HD];
__device__ __align__(16) uint4 wq2[NE * 16 * 4 * HD];
__device__ __align__(16) uint4 wq3[NE * 16 * 4 * HD];

__device__ __forceinline__ float mishf(float v) {
    if (v > 20.f) return v;
    float u = __expf(v);
    float w = 1.f + u;
    w = w * w;
    return v * __fdividef(w - 1.f, w + 1.f);
}

// ---------------- packing helpers ----------------
__device__ __forceinline__ uint2 pack2(float a, float b) {
    __nv_bfloat16 ha = __float2bfloat16_rn(a), hb = __float2bfloat16_rn(b);
    __nv_bfloat16 la = __float2bfloat16_rn(a - __bfloat162float(ha));
    __nv_bfloat16 lb = __float2bfloat16_rn(b - __bfloat162float(hb));
    uint2 r;
    r.x = (uint32_t)*(unsigned short*)&ha | ((uint32_t)*(unsigned short*)&hb << 16);
    r.y = (uint32_t)*(unsigned short*)&la | ((uint32_t)*(unsigned short*)&lb << 16);
    return r;
}

// ---------------- mma.sync (baseline PTX) ----------------
__device__ __forceinline__ void mma_bf16(float* c, const uint32_t* a, uint32_t b0, uint32_t b1) {
    asm volatile(
        "mma.sync.aligned.m16n8k16.row.col.f32.bf16.bf16.f32 "
        "{%0,%1,%2,%3}, {%4,%5,%6,%7}, {%8,%9}, {%0,%1,%2,%3};"
        : "+f"(c[0]), "+f"(c[1]), "+f"(c[2]), "+f"(c[3])
        : "r"(a[0]), "r"(a[1]), "r"(a[2]), "r"(a[3]), "r"(b0), "r"(b1));
}

// ---------------- kernel 1: per-row prep (+ fused weight packing blocks) ----------------
#define PREP_BLOCKS (NB / 8)
#define WCONV_BLOCKS (((NE + 1) * 21 * 4 * HD + 255) / 256)

__global__ void prep_kernel(
    const float* __restrict__ x, const float* __restrict__ sigma,
    const float* __restrict__ state,
    const float* __restrict__ tW1, const float* __restrict__ tb1,
    const float* __restrict__ tW2, const float* __restrict__ tb2,
    const float* __restrict__ eW1, const float* __restrict__ eW2,
    const float* __restrict__ eW3, const float* __restrict__ gW1)
{
    if (blockIdx.x >= PREP_BLOCKS) {
        int i = (blockIdx.x - PREP_BLOCKS) * blockDim.x + threadIdx.x;
        if (i < (NE + 1) * 21 * 4 * HD) {
            int n = i & 255; int r = i >> 8;
            int t = r & 3; int r2 = r >> 2;
            int ks = r2 % 21; int e = r2 / 21;
            int p0 = ks * 8 + t, p1 = p0 + 4;
            const float* W = (e < NE) ? (eW1 + (size_t)e * IND * HD) : gW1;
            size_t k0 = (size_t)(2 * p0) * HD + n;
            size_t k1 = (size_t)(2 * p1) * HD + n;
            uint2 a = pack2(W[k0], W[k0 + HD]);
            uint2 b = pack2(W[k1], W[k1 + HD]);
            wq1[i] = make_uint4(a.x, a.y, b.x, b.y);
        }
        if (i < NE * 16 * 4 * HD) {
            int n = i & 255; int r = i >> 8;
            int t = r & 3; int r2 = r >> 2;
            int ks = r2 & 15; int e = r2 >> 4;
            int p0 = ks * 8 + t, p1 = p0 + 4;
            size_t k0 = ((size_t)e * HD + 2 * p0) * HD + n;
            size_t k1 = ((size_t)e * HD + 2 * p1) * HD + n;
            uint2 a2 = pack2(eW2[k0], eW2[k0 + HD]);
            uint2 b2 = pack2(eW2[k1], eW2[k1 + HD]);
            wq2[i] = make_uint4(a2.x, a2.y, b2.x, b2.y);
            uint2 a3 = pack2(eW3[k0], eW3[k0 + HD]);
            uint2 b3 = pack2(eW3[k1], eW3[k1 + HD]);
            wq3[i] = make_uint4(a3.x, a3.y, b3.x, b3.y);
        }
        return;
    }

    if (blockIdx.x == 0 && threadIdx.x < NE) g_count[threadIdx.x] = 0;
    if (blockIdx.x == 0 && threadIdx.x == NE) g_entropy = 0.f;

    int wid  = (blockIdx.x * blockDim.x + threadIdx.x) >> 5;
    int lane = threadIdx.x & 31;
    int r = wid;

    float sg  = __ldg(&sigma[r]);
    float sd2 = 0.25f;
    float d   = sg - 0.002f;
    float cskip = sd2 / (d * d + sd2);
    float inv = rsqrtf(sg * sg + sd2);
    float cout = d * 0.5f * inv;
    float cin  = inv;
    float rt   = 250.0f * logf(sg + 1e-44f);

    const float FR[8] = { 1.0f, 0.26826957952797246f, 0.07196856730011519f,
                          0.019306977288832496f, 0.005179474679231212f,
                          0.0013894954943731375f, 0.00037275937203149404f,
                          0.0001f };
    float pe[16];
#pragma unroll
    for (int i = 0; i < 8; i++) {
        float s, c;
        sincosf(rt * FR[i], &s, &c);
        pe[i] = s; pe[i + 8] = c;
    }
    float h1 = __ldg(&tb1[lane]);
#pragma unroll
    for (int i = 0; i < 16; i++) h1 = fmaf(pe[i], __ldg(&tW1[i * 32 + lane]), h1);
    {
        float sp = (h1 > 20.f) ? h1 : log1pf(expf(h1));
        h1 = h1 * tanhf(sp);
    }
    float tacc = (lane < 16) ? __ldg(&tb2[lane]) : 0.f;
#pragma unroll
    for (int j = 0; j < 32; j++) {
        float hj = __shfl_sync(0xffffffffu, h1, j);
        if (lane < 16) tacc = fmaf(hj, __ldg(&tW2[j * 16 + lane]), tacc);
    }
    float* row = g_inp + (size_t)r * IND;
    row[lane]      = cin * __ldg(&x[r * 64 + lane]);
    row[32 + lane] = cin * __ldg(&x[r * 64 + 32 + lane]);
    if (lane < 16) row[64 + lane] = tacc;
#pragma unroll
    for (int i = 0; i < 8; i++)
        row[80 + lane + i * 32] = __ldg(&state[r * 256 + lane + i * 32]);
    if (lane == 0) { g_cskip[r] = cskip; g_cout[r] = cout; }
}

// ---------------- expert/gate1 shared HMMA layout ----------------
#define LDA_U 68
#define XSM_META (168 * LDA_U * 8)        // 91392
#define XSM_TOTAL (XSM_META + 3584)

// ---------------- kernel 2a: gate layer-1 via bf16-split HMMA ----------------
__global__ void __launch_bounds__(256, 2) gate1_kernel(const float* __restrict__ gb1)
{
    extern __shared__ char sm[];
    int base = blockIdx.x * 64;

    int tid = threadIdx.x;
    int lane = tid & 31, wid = tid >> 5;
    int wm = wid >> 2, wn = wid & 3;
    int g = lane >> 2, t = lane & 3;

    float* sb1 = (float*)(sm + XSM_META);

    sb1[tid] = gb1[tid];

    // stage 64 sequential rows: A[pair][row]
    {
        int r = tid & 63, q = tid >> 6;           // q in [0,4), 42 pairs each
        const float2* src = (const float2*)(g_inp + (size_t)(base + r) * IND);
        uint2* A0 = (uint2*)sm;
        for (int p = q * 42; p < q * 42 + 42; p++) {
            float2 v = src[p];
            A0[p * LDA_U + r] = pack2(v.x, v.y);
        }
    }
    __syncthreads();

    float c[2][8][4];
#pragma unroll
    for (int a = 0; a < 2; a++)
#pragma unroll
        for (int b = 0; b < 8; b++)
#pragma unroll
            for (int d = 0; d < 4; d++) c[a][b][d] = 0.f;

    const int nbase = wn * 64 + g;
    const int rowA  = wm * 32 + g;
    const uint2* aptr = (const uint2*)sm + t * LDA_U;
    const uint4* wptr = wq1 + (size_t)NE * 21 * 4 * HD + (size_t)t * HD + nbase;
    for (int ks = 0; ks < 21; ks++) {
        uint32_t ah[2][4], al[2][4];
#pragma unroll
        for (int mt = 0; mt < 2; mt++) {
            int row = rowA + mt * 16;
            uint2 v0 = aptr[row];
            uint2 v1 = aptr[row + 8];
            uint2 v2 = aptr[4 * LDA_U + row];
            uint2 v3 = aptr[4 * LDA_U + row + 8];
            ah[mt][0] = v0.x; al[mt][0] = v0.y;
            ah[mt][1] = v1.x; al[mt][1] = v1.y;
            ah[mt][2] = v2.x; al[mt][2] = v2.y;
            ah[mt][3] = v3.x; al[mt][3] = v3.y;
        }
        uint4 b[8];
#pragma unroll
        for (int nt = 0; nt < 8; nt++) b[nt] = __ldg(wptr + nt * 8);
#pragma unroll
        for (int nt = 0; nt < 8; nt++)
#pragma unroll
            for (int mt = 0; mt < 2; mt++)
                mma_bf16(c[mt][nt], ah[mt], b[nt].x, b[nt].z);
#pragma unroll
        for (int nt = 0; nt < 8; nt++)
#pragma unroll
            for (int mt = 0; mt < 2; mt++)
                mma_bf16(c[mt][nt], ah[mt], b[nt].y, b[nt].w);
#pragma unroll
        for (int nt = 0; nt < 8; nt++)
#pragma unroll
            for (int mt = 0; mt < 2; mt++)
                mma_bf16(c[mt][nt], al[mt], b[nt].x, b[nt].z);
        aptr += 8 * LDA_U;
        wptr += 4 * HD;
    }

    // epilogue: relu(c + b1) -> g_g1
#pragma unroll
    for (int mt = 0; mt < 2; mt++) {
#pragma unroll
        for (int half = 0; half < 2; half++) {
            int m = wm * 32 + mt * 16 + half * 8 + g;
            float* dst = g_g1 + (size_t)(base + m) * HD;
#pragma unroll
            for (int nt = 0; nt < 8; nt++) {
                int col = wn * 64 + nt * 8 + 2 * t;
                float2 o;
                o.x = fmaxf(c[mt][nt][half * 2 + 0] + sb1[col], 0.f);
                o.y = fmaxf(c[mt][nt][half * 2 + 1] + sb1[col + 1], 0.f);
                *(float2*)&dst[col] = o;
            }
        }
    }
}

// ---------------- kernel 2b: gate layer-2 + softmax + top4 + routing ----------------
__global__ void __launch_bounds__(256, 2) gate2_kernel(
    const float* __restrict__ gW2, const float* __restrict__ gb2)
{
    extern __shared__ float smem[];
    float* G1s  = smem;             // 64*256
    float* W2t  = G1s + 64 * 256;   // 16*260 (transposed)
    float* entA = W2t + 16 * 260;   // 1

    int tid = threadIdx.x, ty = tid >> 5, tx = tid & 31;
    int base = blockIdx.x * 64;
    if (tid == 0) *entA = 0.f;
    for (int i = tid; i < 4096; i += 256)
        ((float4*)G1s)[i] = *(const float4*)&g_g1[(size_t)base * HD + i * 4];
    for (int i = tid; i < 4096; i += 256) {
        int k = i >> 4, j = i & 15;
        W2t[j * 260 + k] = gW2[k * 16 + j];
    }
    __syncthreads();

    int j = tx & 15, h = tx >> 4;
    const float* wrow = &W2t[j * 260];
    for (int rr = 0; rr < 4; rr++) {
        int m = ty * 8 + rr * 2 + h;
        int row = base + m;
        const float* g1 = &G1s[m * 256];
        float s0 = 0.f, s1 = 0.f, s2 = 0.f, s3 = 0.f;
#pragma unroll
        for (int k = 0; k < 256; k += 16) {
            float4 a0 = *(const float4*)&g1[k];
            float4 w0 = *(const float4*)&wrow[k];
            float4 a1 = *(const float4*)&g1[k + 4];
            float4 w1 = *(const float4*)&wrow[k + 4];
            float4 a2 = *(const float4*)&g1[k + 8];
            float4 w2 = *(const float4*)&wrow[k + 8];
            float4 a3 = *(const float4*)&g1[k + 12];
            float4 w3 = *(const float4*)&wrow[k + 12];
            s0 = fmaf(a0.x, w0.x, s0); s0 = fmaf(a0.y, w0.y, s0);
            s0 = fmaf(a0.z, w0.z, s0); s0 = fmaf(a0.w, w0.w, s0);
            s1 = fmaf(a1.x, w1.x, s1); s1 = fmaf(a1.y, w1.y, s1);
            s1 = fmaf(a1.z, w1.z, s1); s1 = fmaf(a1.w, w1.w, s1);
            s2 = fmaf(a2.x, w2.x, s2); s2 = fmaf(a2.y, w2.y, s2);
            s2 = fmaf(a2.z, w2.z, s2); s2 = fmaf(a2.w, w2.w, s2);
            s3 = fmaf(a3.x, w3.x, s3); s3 = fmaf(a3.y, w3.y, s3);
            s3 = fmaf(a3.z, w3.z, s3); s3 = fmaf(a3.w, w3.w, s3);
        }
        float gv = (s0 + s1) + (s2 + s3) + __ldg(&gb2[j]);
        float p[16];
#pragma unroll
        for (int q = 0; q < 16; q++) p[q] = __shfl_sync(0xffffffffu, gv, q, 16);
        float mx = p[0];
#pragma unroll
        for (int q = 1; q < 16; q++) mx = fmaxf(mx, p[q]);
        float Z = 0.f;
#pragma unroll
        for (int q = 0; q < 16; q++) { p[q] = expf(p[q] - mx); Z += p[q]; }
        float invZ = 1.f / Z;
        float ent = 0.f;
#pragma unroll
        for (int q = 0; q < 16; q++) { p[q] *= invZ; ent -= p[q] * logf(p[q] + 1e-9f); }
        unsigned usedm = 0;
        int   idx[4]; float val[4]; float wsum = 0.f;
#pragma unroll
        for (int s4 = 0; s4 < 4; s4++) {
            int best = 0; float bv = -1.f;
#pragma unroll
            for (int q = 0; q < 16; q++) {
                bool free = !((usedm >> q) & 1u);
                if (free && p[q] > bv) { bv = p[q]; best = q; }
            }
            usedm |= (1u << best);
            idx[s4] = best; val[s4] = bv; wsum += bv;
        }
        float invw = 1.f / (wsum + 1e-9f);
        if (j < 4) {
            int ee = idx[j];
            int pos = atomicAdd(&g_count[ee], 1);
            g_bucket[ee * NB + pos] = row | (j << 16);
            g_bw[ee * NB + pos] = val[j] * invw;
        }
        if (j == 0) atomicAdd(entA, ent);
    }
    __syncthreads();
    if (tid == 0) atomicAdd(&g_entropy, *entA);
}

// ---------------- kernel 3: bf16-split HMMA expert MLP (R10 config) ----------------
__global__ void __launch_bounds__(256, 2) expert_kernel(
    const float* __restrict__ eb1, const float* __restrict__ eb2,
    const float* __restrict__ eb3)
{
    extern __shared__ char sm[];
    int e = blockIdx.y;
    int cnt = g_count[e];
    int base = blockIdx.x * 64;
    if (base >= cnt) return;

    int tid = threadIdx.x;
    int lane = tid & 31, wid = tid >> 5;
    int wm = wid >> 2, wn = wid & 3;
    int g = lane >> 2, t = lane & 3;

    int*   srow = (int*)(sm + XSM_META);
    float* swt  = (float*)(sm + XSM_META + 256);
    float* sb1  = (float*)(sm + XSM_META + 512);
    float* sb2  = (float*)(sm + XSM_META + 1536);
    float* sb3  = (float*)(sm + XSM_META + 2560);

    if (tid < 64) {
        int gi = base + tid;
        int gj = (gi < cnt) ? gi : (cnt - 1);
        srow[tid] = g_bucket[e * NB + gj];
        swt[tid]  = (gi < cnt) ? g_bw[e * NB + gj] : 0.f;
    }
    sb1[tid] = eb1[e * HD + tid];
    sb2[tid] = eb2[e * HD + tid];
    sb3[tid] = eb3[e * HD + tid];
    __syncthreads();

    {
        int r = tid & 63, q = tid >> 6;
        int rid = srow[r] & 0xFFFF;
        const float2* src = (const float2*)(g_inp + (size_t)rid * IND);
        uint2* A0 = (uint2*)sm;
        for (int p = q * 42; p < q * 42 + 42; p++) {
            float2 v = src[p];
            A0[p * LDA_U + r] = pack2(v.x, v.y);
        }
    }
    __syncthreads();

    float c[2][8][4];
    const int nbase = wn * 64 + g;
    const int rowA  = wm * 32 + g;

    auto run_layer = [&](const uint4* __restrict__ wq, int ksteps) {
#pragma unroll
        for (int a = 0; a < 2; a++)
#pragma unroll
            for (int b = 0; b < 8; b++)
#pragma unroll
                for (int d = 0; d < 4; d++) c[a][b][d] = 0.f;
        const uint2* aptr = (const uint2*)sm + t * LDA_U;
        const uint4* wptr = wq + (size_t)t * HD + nbase;
        for (int ks = 0; ks < ksteps; ks++) {
            uint32_t ah[2][4], al[2][4];
#pragma unroll
            for (int mt = 0; mt < 2; mt++) {
                int row = rowA + mt * 16;
                uint2 v0 = aptr[row];
                uint2 v1 = aptr[row + 8];
                uint2 v2 = aptr[4 * LDA_U + row];
                uint2 v3 = aptr[4 * LDA_U + row + 8];
                ah[mt][0] = v0.x; al[mt][0] = v0.y;
                ah[mt][1] = v1.x; al[mt][1] = v1.y;
                ah[mt][2] = v2.x; al[mt][2] = v2.y;
                ah[mt][3] = v3.x; al[mt][3] = v3.y;
            }
            uint4 b[8];
#pragma unroll
            for (int nt = 0; nt < 8; nt++) b[nt] = __ldg(wptr + nt * 8);
#pragma unroll
            for (int nt = 0; nt < 8; nt++)
#pragma unroll
                for (int mt = 0; mt < 2; mt++)
                    mma_bf16(c[mt][nt], ah[mt], b[nt].x, b[nt].z);
#pragma unroll
            for (int nt = 0; nt < 8; nt++)
#pragma unroll
                for (int mt = 0; mt < 2; mt++)
                    mma_bf16(c[mt][nt], ah[mt], b[nt].y, b[nt].w);
#pragma unroll
            for (int nt = 0; nt < 8; nt++)
#pragma unroll
                for (int mt = 0; mt < 2; mt++)
                    mma_bf16(c[mt][nt], al[mt], b[nt].x, b[nt].z);
            aptr += 8 * LDA_U;
            wptr += 4 * HD;
        }
        __syncthreads();
    };

    auto write_act = [&](const float* sb) {
        uint2* An = (uint2*)sm;
#pragma unroll
        for (int mt = 0; mt < 2; mt++) {
            int row0 = rowA + mt * 16;
#pragma unroll
            for (int nt = 0; nt < 8; nt++) {
                int col = wn * 64 + nt * 8 + 2 * t;
                int p = wn * 32 + nt * 4 + t;
                float b0 = sb[col], b1 = sb[col + 1];
                An[p * LDA_U + row0]     = pack2(mishf(c[mt][nt][0] + b0), mishf(c[mt][nt][1] + b1));
                An[p * LDA_U + row0 + 8] = pack2(mishf(c[mt][nt][2] + b0), mishf(c[mt][nt][3] + b1));
            }
        }
        __syncthreads();
    };

    run_layer(wq1 + (size_t)e * 21 * 4 * HD, 21);
    write_act(sb1);
    run_layer(wq2 + (size_t)e * 16 * 4 * HD, 16);
    write_act(sb2);
    run_layer(wq3 + (size_t)e * 16 * 4 * HD, 16);

#pragma unroll
    for (int mt = 0; mt < 2; mt++) {
#pragma unroll
        for (int half = 0; half < 2; half++) {
            int m = wm * 32 + mt * 16 + half * 8 + g;
            int gi = base + m;
            if (gi < cnt) {
                int packed = srow[m];
                int row = packed & 0xFFFF, slot = packed >> 16;
                float w = swt[m];
                float* dst = g_eout + ((size_t)(row * 4 + slot)) * HD;
#pragma unroll
                for (int nt = 0; nt < 8; nt++) {
                    int col = wn * 64 + nt * 8 + 2 * t;
                    float2 o;
                    o.x = w * mishf(c[mt][nt][half * 2 + 0] + sb3[col]);
                    o.y = w * mishf(c[mt][nt][half * 2 + 1] + sb3[col + 1]);
                    *(float2*)&dst[col] = o;
                }
            }
        }
    }
}

// ---------------- kernel 4: combine slots + final linear + epilogue + aux ----------------
__global__ void __launch_bounds__(256, 2) final_kernel(
    const float* __restrict__ x, const float* __restrict__ fW,
    const float* __restrict__ fb, float* __restrict__ out, int out_size)
{
    extern __shared__ float smem[];
    float* cs  = smem;             // 32*260
    float* fWs = cs + 32 * 260;    // 256*64
    int tid = threadIdx.x;
    int base = blockIdx.x * 32;

    for (int i = tid; i < 4096; i += 256)
        ((float4*)fWs)[i] = ((const float4*)fW)[i];
    for (int idx = tid; idx < 32 * 64; idx += 256) {
        int m = idx >> 6, n4 = (idx & 63) << 2;
        size_t rb = ((size_t)(base + m)) * 4 * HD + n4;
        float4 a = *(const float4*)&g_eout[rb];
        float4 b = *(const float4*)&g_eout[rb + 256];
        float4 c = *(const float4*)&g_eout[rb + 512];
        float4 d = *(const float4*)&g_eout[rb + 768];
        float4 v;
        v.x = a.x + b.x + c.x + d.x;
        v.y = a.y + b.y + c.y + d.y;
        v.z = a.z + b.z + c.z + d.z;
        v.w = a.w + b.w + c.w + d.w;
        *(float4*)&cs[m * 260 + n4] = v;
    }
    __syncthreads();

    int ty = tid >> 4, tx = tid & 15;
    float acc[2][4];
#pragma unroll
    for (int mi = 0; mi < 2; mi++)
#pragma unroll
        for (int ci = 0; ci < 4; ci++) acc[mi][ci] = 0.f;
#pragma unroll 4
    for (int k = 0; k < 256; k++) {
        float4 b = *(const float4*)&fWs[k * 64 + (tx << 2)];
#pragma unroll
        for (int mi = 0; mi < 2; mi++) {
            float a = cs[(ty * 2 + mi) * 260 + k];
            acc[mi][0] = fmaf(a, b.x, acc[mi][0]);
            acc[mi][1] = fmaf(a, b.y, acc[mi][1]);
            acc[mi][2] = fmaf(a, b.z, acc[mi][2]);
            acc[mi][3] = fmaf(a, b.w, acc[mi][3]);
        }
    }
#pragma unroll
    for (int mi = 0; mi < 2; mi++) {
        int row = base + ty * 2 + mi;
        float co = g_cout[row], ck = g_cskip[row];
        float4 xr = *(const float4*)&x[row * 64 + (tx << 2)];
        float4 o;
        o.x = fminf(fmaxf(co * (acc[mi][0] + __ldg(&fb[(tx << 2) + 0])) + ck * xr.x, -1.f), 1.f);
        o.y = fminf(fmaxf(co * (acc[mi][1] + __ldg(&fb[(tx << 2) + 1])) + ck * xr.y, -1.f), 1.f);
        o.z = fminf(fmaxf(co * (acc[mi][2] + __ldg(&fb[(tx << 2) + 2])) + ck * xr.z, -1.f), 1.f);
        o.w = fminf(fmaxf(co * (acc[mi][3] + __ldg(&fb[(tx << 2) + 3])) + ck * xr.w, -1.f), 1.f);
        *(float4*)&out[row * 64 + (tx << 2)] = o;
    }

    if (blockIdx.x == 0 && tid == 0 && out_size > NB * NACT) {
        float load[NE], mean = 0.f;
#pragma unroll
        for (int e = 0; e < NE; e++) { load[e] = (float)g_count[e] / (32768.0f + 1e-9f); mean += load[e]; }
        mean *= (1.0f / NE);
        float var = 0.f;
#pragma unroll
        for (int e = 0; e < NE; e++) { float d = load[e] - mean; var += d * d; }
        var *= (1.0f / (NE - 1));
        out[NB * NACT] = var + g_entropy / 32768.0f;
    }
}

extern "C" void kernel_launch(void* const* d_in, const int* in_sizes, int n_in,
                              void* d_out, int out_size)
{
    const float* x     = (const float*)d_in[0];
    const float* sigma = (const float*)d_in[1];
    const float* state = (const float*)d_in[2];
    const float* tW1 = (const float*)d_in[3];
    const float* tb1 = (const float*)d_in[4];
    const float* tW2 = (const float*)d_in[5];
    const float* tb2 = (const float*)d_in[6];
    const float* gW1 = (const float*)d_in[7];
    const float* gb1 = (const float*)d_in[8];
    const float* gW2 = (const float*)d_in[9];
    const float* gb2 = (const float*)d_in[10];
    const float* eW1 = (const float*)d_in[11];
    const float* eb1 = (const float*)d_in[12];
    const float* eW2 = (const float*)d_in[13];
    const float* eb2 = (const float*)d_in[14];
    const float* eW3 = (const float*)d_in[15];
    const float* eb3 = (const float*)d_in[16];
    const float* fW  = (const float*)d_in[17];
    const float* fb  = (const float*)d_in[18];
    float* out = (float*)d_out;

    const int gate2Smem = (64 * 256 + 16 * 260 + 16) * 4;         // 82240
    const int finSmem   = (32 * 260 + 256 * 64 + 16) * 4;         // 98880
    cudaFuncSetAttribute(gate1_kernel,  cudaFuncAttributeMaxDynamicSharedMemorySize, XSM_TOTAL);
    cudaFuncSetAttribute(gate2_kernel,  cudaFuncAttributeMaxDynamicSharedMemorySize, gate2Smem);
    cudaFuncSetAttribute(expert_kernel, cudaFuncAttributeMaxDynamicSharedMemorySize, XSM_TOTAL);
    cudaFuncSetAttribute(final_kernel,  cudaFuncAttributeMaxDynamicSharedMemorySize, finSmem);

    prep_kernel<<<PREP_BLOCKS + WCONV_BLOCKS, 256>>>(
        x, sigma, state, tW1, tb1, tW2, tb2, eW1, eW2, eW3, gW1);
    gate1_kernel<<<NB / 64, 256, XSM_TOTAL>>>(gb1);
    gate2_kernel<<<NB / 64, 256, gate2Smem>>>(gW2, gb2);
    expert_kernel<<<dim3(NB / 64, NE), 256, XSM_TOTAL>>>(eb1, eb2, eb3);
    final_kernel<<<NB / 32, 256, finSmem>>>(x, fW, fb, out, out_size);
}